// round 5
// baseline (speedup 1.0000x reference)
#include <cuda_runtime.h>
#include <cuda_bf16.h>
#include <cstdint>

#define BB 16
#define DD 1024
#define QQ 128
#define HH 1024

// ---------------- scratch (device globals) ----------------------------------
__device__ float g_S [BB * DD * QQ];
__device__ float g_sd[BB * DD];
__device__ float g_sq[BB * QQ];
// pre-split bf16 hi/lo operand arrays
__device__ __nv_bfloat16 g_Udh [BB * DD * HH], g_Udl [BB * DD * HH];  // Ud  [b,d,h]
__device__ __nv_bfloat16 g_Udth[BB * HH * DD], g_Udtl[BB * HH * DD];  // Ud^T [b,h,d]
__device__ __nv_bfloat16 g_Uqwh[BB * QQ * HH], g_Uqwl[BB * QQ * HH];  // Uq*wdot [b,q,h]
__device__ __nv_bfloat16 g_Uqth[BB * HH * QQ], g_Uqtl[BB * HH * QQ];  // Uq^T [b,h,q]
__device__ __nv_bfloat16 g_P1h [BB * DD * QQ], g_P1l [BB * DD * QQ];  // S_d2q [b,d,q]
__device__ __nv_bfloat16 g_P2th[BB * QQ * DD], g_P2tl[BB * QQ * DD];  // S_q2d^T [b,q,d]
__device__ __nv_bfloat16 g_Tth [BB * HH * QQ], g_Ttl [BB * HH * QQ];  // T^T [b,h,q]

// ---------------- helpers ----------------------------------------------------
#define SROW 40   // smem row stride in bf16 elements (80 B)

__device__ __forceinline__ uint32_t L32(const __nv_bfloat16* p) {
    return *(const uint32_t*)p;
}
__device__ __forceinline__ void mma_bf16(float* c, const uint32_t* a, const uint32_t* b) {
    asm volatile(
        "mma.sync.aligned.m16n8k16.row.col.f32.bf16.bf16.f32 "
        "{%0,%1,%2,%3}, {%4,%5,%6,%7}, {%8,%9}, {%0,%1,%2,%3};"
        : "+f"(c[0]), "+f"(c[1]), "+f"(c[2]), "+f"(c[3])
        : "r"(a[0]), "r"(a[1]), "r"(a[2]), "r"(a[3]), "r"(b[0]), "r"(b[1]));
}
__device__ __forceinline__ void bsplit(float x, __nv_bfloat16& h, __nv_bfloat16& l) {
    h = __float2bfloat16(x);
    l = __float2bfloat16(x - __bfloat162float(h));
}

// one k16 step: 4x4 m16n8 tiles, 3 precision passes
#define K16_STEP(kb)                                                          \
    do {                                                                      \
        uint32_t ah[4][4], al[4][4], bh[4][2], bl[4][2];                      \
        _Pragma("unroll")                                                     \
        for (int i = 0; i < 4; i++) {                                         \
            int r = wm * 64 + i * 16 + gr;                                    \
            const __nv_bfloat16* p = sAh + r * SROW + (kb) + 2 * qp;          \
            const __nv_bfloat16* q = sAl + r * SROW + (kb) + 2 * qp;          \
            ah[i][0] = L32(p);            ah[i][1] = L32(p + 8 * SROW);       \
            ah[i][2] = L32(p + 8);        ah[i][3] = L32(p + 8 * SROW + 8);   \
            al[i][0] = L32(q);            al[i][1] = L32(q + 8 * SROW);       \
            al[i][2] = L32(q + 8);        al[i][3] = L32(q + 8 * SROW + 8);   \
        }                                                                     \
        _Pragma("unroll")                                                     \
        for (int j = 0; j < 4; j++) {                                         \
            int c = wn * 32 + j * 8 + gr;                                     \
            const __nv_bfloat16* p = sBh + c * SROW + (kb) + 2 * qp;          \
            const __nv_bfloat16* q = sBl + c * SROW + (kb) + 2 * qp;          \
            bh[j][0] = L32(p); bh[j][1] = L32(p + 8);                         \
            bl[j][0] = L32(q); bl[j][1] = L32(q + 8);                         \
        }                                                                     \
        _Pragma("unroll")                                                     \
        for (int i = 0; i < 4; i++)                                           \
            _Pragma("unroll")                                                 \
            for (int j = 0; j < 4; j++) mma_bf16(acc[i][j], ah[i], bh[j]);    \
        _Pragma("unroll")                                                     \
        for (int i = 0; i < 4; i++)                                           \
            _Pragma("unroll")                                                 \
            for (int j = 0; j < 4; j++) mma_bf16(acc[i][j], ah[i], bl[j]);    \
        _Pragma("unroll")                                                     \
        for (int i = 0; i < 4; i++)                                           \
            _Pragma("unroll")                                                 \
            for (int j = 0; j < 4; j++) mma_bf16(acc[i][j], al[i], bh[j]);    \
    } while (0)

#define GEMM_PREAMBLE                                                         \
    __shared__ __nv_bfloat16 sAh[128 * SROW], sAl[128 * SROW];                \
    __shared__ __nv_bfloat16 sBh[128 * SROW], sBl[128 * SROW];                \
    int t = threadIdx.x;                                                      \
    int wid = t >> 5, lane = t & 31;                                          \
    int wm = wid >> 2, wn = wid & 3;                                          \
    int gr = lane >> 2, qp = lane & 3;                                        \
    float acc[4][4][4];                                                       \
    _Pragma("unroll")                                                         \
    for (int i = 0; i < 4; i++)                                               \
        _Pragma("unroll")                                                     \
        for (int j = 0; j < 4; j++)                                           \
            _Pragma("unroll")                                                 \
            for (int e = 0; e < 4; e++) acc[i][j][e] = 0.f;                   \
    uint4 pAh0, pAh1, pAl0, pAl1, pBh0, pBh1, pBl0, pBl1;                     \
    int srow = t >> 2, srow2 = (t >> 2) + 64, kc = (t & 3) * 8;

#define PREF(Ah, Al, Bh, Bl, lda, ldb, k0)                                    \
    pAh0 = *(const uint4*)((Ah) + (size_t)srow  * (lda) + (k0) + kc);         \
    pAh1 = *(const uint4*)((Ah) + (size_t)srow2 * (lda) + (k0) + kc);         \
    pAl0 = *(const uint4*)((Al) + (size_t)srow  * (lda) + (k0) + kc);         \
    pAl1 = *(const uint4*)((Al) + (size_t)srow2 * (lda) + (k0) + kc);         \
    pBh0 = *(const uint4*)((Bh) + (size_t)srow  * (ldb) + (k0) + kc);         \
    pBh1 = *(const uint4*)((Bh) + (size_t)srow2 * (ldb) + (k0) + kc);         \
    pBl0 = *(const uint4*)((Bl) + (size_t)srow  * (ldb) + (k0) + kc);         \
    pBl1 = *(const uint4*)((Bl) + (size_t)srow2 * (ldb) + (k0) + kc);

#define STS_ALL                                                               \
    *(uint4*)&sAh[srow  * SROW + kc] = pAh0;                                  \
    *(uint4*)&sAh[srow2 * SROW + kc] = pAh1;                                  \
    *(uint4*)&sAl[srow  * SROW + kc] = pAl0;                                  \
    *(uint4*)&sAl[srow2 * SROW + kc] = pAl1;                                  \
    *(uint4*)&sBh[srow  * SROW + kc] = pBh0;                                  \
    *(uint4*)&sBh[srow2 * SROW + kc] = pBh1;                                  \
    *(uint4*)&sBl[srow  * SROW + kc] = pBl0;                                  \
    *(uint4*)&sBl[srow2 * SROW + kc] = pBl1;

// ---------------- conversion kernels ----------------------------------------
// Ud -> (Udh,Udl)[d,h] and (Udth,Udtl)[h,d]
__global__ void conv_ud_kernel(const float* __restrict__ Ud) {
    __shared__ float tile[32][33];
    int b = blockIdx.z, h0 = blockIdx.x * 32, d0 = blockIdx.y * 32;
    int tx = threadIdx.x, ty = threadIdx.y;
    const float* src = Ud + (size_t)b * DD * HH;
    for (int i = ty; i < 32; i += 8) {
        float v = src[(size_t)(d0 + i) * HH + h0 + tx];
        tile[i][tx] = v;
        __nv_bfloat16 h, l; bsplit(v, h, l);
        size_t o = (size_t)b * DD * HH + (size_t)(d0 + i) * HH + h0 + tx;
        g_Udh[o] = h; g_Udl[o] = l;
    }
    __syncthreads();
    for (int i = ty; i < 32; i += 8) {
        float v = tile[tx][i];
        __nv_bfloat16 h, l; bsplit(v, h, l);
        size_t o = (size_t)b * HH * DD + (size_t)(h0 + i) * DD + d0 + tx;
        g_Udth[o] = h; g_Udtl[o] = l;
    }
}

// Uq -> (Uqwh,Uqwl)[q,h] (x wdot) and (Uqth,Uqtl)[h,q]
__global__ void conv_uq_kernel(const float* __restrict__ Uq,
                               const float* __restrict__ wdot) {
    __shared__ float tile[32][33];
    int b = blockIdx.z, h0 = blockIdx.x * 32, q0 = blockIdx.y * 32;
    int tx = threadIdx.x, ty = threadIdx.y;
    const float* src = Uq + (size_t)b * QQ * HH;
    float w = wdot[h0 + tx];
    for (int i = ty; i < 32; i += 8) {
        float v = src[(size_t)(q0 + i) * HH + h0 + tx];
        tile[i][tx] = v;
        __nv_bfloat16 h, l; bsplit(v * w, h, l);
        size_t o = (size_t)b * QQ * HH + (size_t)(q0 + i) * HH + h0 + tx;
        g_Uqwh[o] = h; g_Uqwl[o] = l;
    }
    __syncthreads();
    for (int i = ty; i < 32; i += 8) {
        float v = tile[tx][i];
        __nv_bfloat16 h, l; bsplit(v, h, l);
        size_t o = (size_t)b * HH * QQ + (size_t)(h0 + i) * QQ + q0 + tx;
        g_Uqth[o] = h; g_Uqtl[o] = l;
    }
}

// ---------------- row dots ---------------------------------------------------
__global__ void rowdot_kernel(const float* __restrict__ X,
                              const float* __restrict__ w, int nrows, int mode) {
    int gw = (blockIdx.x * blockDim.x + threadIdx.x) >> 5;
    int lane = threadIdx.x & 31;
    if (gw >= nrows) return;
    const float* row = X + (size_t)gw * HH;
    float s = 0.f;
    #pragma unroll
    for (int k = lane * 4; k < HH; k += 128) {
        float4 v = *(const float4*)(row + k);
        float4 ww = *(const float4*)(w + k);
        s += v.x * ww.x + v.y * ww.y + v.z * ww.z + v.w * ww.w;
    }
    #pragma unroll
    for (int o = 16; o; o >>= 1) s += __shfl_xor_sync(0xffffffffu, s, o);
    if (lane == 0) { if (mode == 0) g_sd[gw] = s; else g_sq[gw] = s; }
}

// ---------------- GEMM1: S = Ud @ (Uq*wdot)^T + sd + sq + bias ---------------
__global__ __launch_bounds__(256) void gemm1_mma(const float* __restrict__ wcb) {
    GEMM_PREAMBLE
    int b = blockIdx.y, m0 = blockIdx.x * 128;
    const __nv_bfloat16* Ah = g_Udh + (size_t)b * DD * HH + (size_t)m0 * HH;
    const __nv_bfloat16* Al = g_Udl + (size_t)b * DD * HH + (size_t)m0 * HH;
    const __nv_bfloat16* Bh = g_Uqwh + (size_t)b * QQ * HH;
    const __nv_bfloat16* Bl = g_Uqwl + (size_t)b * QQ * HH;

    PREF(Ah, Al, Bh, Bl, HH, HH, 0)
    for (int k0 = 0; k0 < HH; k0 += 32) {
        __syncthreads();
        STS_ALL
        __syncthreads();
        if (k0 + 32 < HH) { PREF(Ah, Al, Bh, Bl, HH, HH, k0 + 32) }
        K16_STEP(0);
        K16_STEP(16);
    }

    float bias = wcb[0];
    #pragma unroll
    for (int i = 0; i < 4; i++) {
        int m = m0 + wm * 64 + i * 16 + gr;
        float sd0 = g_sd[b * DD + m] + bias;
        float sd1 = g_sd[b * DD + m + 8] + bias;
        #pragma unroll
        for (int j = 0; j < 4; j++) {
            int n = wn * 32 + j * 8 + 2 * qp;
            float sq0 = g_sq[b * QQ + n], sq1 = g_sq[b * QQ + n + 1];
            float* d0 = g_S + ((size_t)b * DD + m) * QQ + n;
            float* d1 = g_S + ((size_t)b * DD + m + 8) * QQ + n;
            *(float2*)d0 = make_float2(acc[i][j][0] + sd0 + sq0, acc[i][j][1] + sd0 + sq1);
            *(float2*)d1 = make_float2(acc[i][j][2] + sd1 + sq0, acc[i][j][3] + sd1 + sq1);
        }
    }
}

// ---------------- GEMM3: Tt[h,q] = sum_d Udt[h,d]*P2t[q,d] -> bf16 split -----
__global__ __launch_bounds__(256) void gemm3_mma() {
    GEMM_PREAMBLE
    int b = blockIdx.y, m0 = blockIdx.x * 128;
    const __nv_bfloat16* Ah = g_Udth + (size_t)b * HH * DD + (size_t)m0 * DD;
    const __nv_bfloat16* Al = g_Udtl + (size_t)b * HH * DD + (size_t)m0 * DD;
    const __nv_bfloat16* Bh = g_P2th + (size_t)b * QQ * DD;
    const __nv_bfloat16* Bl = g_P2tl + (size_t)b * QQ * DD;

    PREF(Ah, Al, Bh, Bl, DD, DD, 0)
    for (int k0 = 0; k0 < DD; k0 += 32) {
        __syncthreads();
        STS_ALL
        __syncthreads();
        if (k0 + 32 < DD) { PREF(Ah, Al, Bh, Bl, DD, DD, k0 + 32) }
        K16_STEP(0);
        K16_STEP(16);
    }

    #pragma unroll
    for (int i = 0; i < 4; i++) {
        int m = m0 + wm * 64 + i * 16 + gr;
        #pragma unroll
        for (int j = 0; j < 4; j++) {
            int n = wn * 32 + j * 8 + 2 * qp;
            #pragma unroll
            for (int rr = 0; rr < 2; rr++) {
                float a0 = acc[i][j][2 * rr], a1 = acc[i][j][2 * rr + 1];
                __nv_bfloat16 h0, l0, h1, l1;
                bsplit(a0, h0, l0); bsplit(a1, h1, l1);
                size_t o = ((size_t)b * HH + m + rr * 8) * QQ + n;
                *(__nv_bfloat162*)(g_Tth + o) = __nv_bfloat162(h0, h1);
                *(__nv_bfloat162*)(g_Ttl + o) = __nv_bfloat162(l0, l1);
            }
        }
    }
}

// ---------------- GEMM2/4: C[d,h] = sum_q P1[d,q] * Bt[h,q] ------------------
__global__ __launch_bounds__(256) void gemm24_mma(
    const float* __restrict__ Ud, float* __restrict__ out, int mode) {
    GEMM_PREAMBLE
    int b = blockIdx.z, n0 = blockIdx.x * 128, m0 = blockIdx.y * 128;
    const __nv_bfloat16* Ah = g_P1h + (size_t)b * DD * QQ + (size_t)m0 * QQ;
    const __nv_bfloat16* Al = g_P1l + (size_t)b * DD * QQ + (size_t)m0 * QQ;
    const __nv_bfloat16* Bh = ((mode == 0) ? g_Uqth : g_Tth) + (size_t)b * HH * QQ + (size_t)n0 * QQ;
    const __nv_bfloat16* Bl = ((mode == 0) ? g_Uqtl : g_Ttl) + (size_t)b * HH * QQ + (size_t)n0 * QQ;

    PREF(Ah, Al, Bh, Bl, QQ, QQ, 0)
    for (int k0 = 0; k0 < QQ; k0 += 32) {
        __syncthreads();
        STS_ALL
        __syncthreads();
        if (k0 + 32 < QQ) { PREF(Ah, Al, Bh, Bl, QQ, QQ, k0 + 32) }
        K16_STEP(0);
        K16_STEP(16);
    }

    #pragma unroll
    for (int i = 0; i < 4; i++) {
        int m = m0 + wm * 64 + i * 16 + gr;
        #pragma unroll
        for (int j = 0; j < 4; j++) {
            int n = n0 + wn * 32 + j * 8 + 2 * qp;
            #pragma unroll
            for (int rr = 0; rr < 2; rr++) {
                int mm = m + rr * 8;
                float a0 = acc[i][j][2 * rr], a1 = acc[i][j][2 * rr + 1];
                float2 u = *(const float2*)(Ud + ((size_t)b * DD + mm) * HH + n);
                float* ob = out + ((size_t)b * DD + mm) * (size_t)(4 * HH) + n;
                if (mode == 0) {
                    *(float2*)(ob)          = u;
                    *(float2*)(ob + HH)     = make_float2(a0, a1);
                    *(float2*)(ob + 2 * HH) = make_float2(u.x * a0, u.y * a1);
                } else {
                    *(float2*)(ob + 3 * HH) = make_float2(u.x * a0, u.y * a1);
                }
            }
        }
    }
}

// ---------------- softmax over q (axis -1): g_S -> P1 hi/lo ------------------
__global__ void softmax_d2q_kernel(const int* __restrict__ qm,
                                   const int* __restrict__ dmk) {
    int row = (blockIdx.x * blockDim.x + threadIdx.x) >> 5;
    if (row >= BB * DD) return;
    int lane = threadIdx.x & 31;
    int b = row >> 10;
    int dmv = dmk[row];
    const float* src = g_S + (size_t)row * QQ;
    float4 v = *(const float4*)(src + lane * 4);
    int4 q4 = *(const int4*)(qm + b * QQ + lane * 4);
    int mk0 = (dmv > 0) && (q4.x > 0), mk1 = (dmv > 0) && (q4.y > 0);
    int mk2 = (dmv > 0) && (q4.z > 0), mk3 = (dmv > 0) && (q4.w > 0);
    float l0 = mk0 ? v.x : -1e30f, l1 = mk1 ? v.y : -1e30f;
    float l2 = mk2 ? v.z : -1e30f, l3 = mk3 ? v.w : -1e30f;
    float mx = fmaxf(fmaxf(l0, l1), fmaxf(l2, l3));
    #pragma unroll
    for (int o = 16; o; o >>= 1) mx = fmaxf(mx, __shfl_xor_sync(0xffffffffu, mx, o));
    float e0 = __expf(l0 - mx), e1 = __expf(l1 - mx);
    float e2 = __expf(l2 - mx), e3 = __expf(l3 - mx);
    float s = e0 + e1 + e2 + e3;
    #pragma unroll
    for (int o = 16; o; o >>= 1) s += __shfl_xor_sync(0xffffffffu, s, o);
    float inv = 1.f / s;
    float p0 = mk0 ? e0 * inv : 0.f, p1 = mk1 ? e1 * inv : 0.f;
    float p2 = mk2 ? e2 * inv : 0.f, p3 = mk3 ? e3 * inv : 0.f;
    __nv_bfloat16 h0, lo0, h1, lo1, h2, lo2, h3, lo3;
    bsplit(p0, h0, lo0); bsplit(p1, h1, lo1);
    bsplit(p2, h2, lo2); bsplit(p3, h3, lo3);
    size_t o = (size_t)row * QQ + lane * 4;
    *(__nv_bfloat162*)(g_P1h + o)     = __nv_bfloat162(h0, h1);
    *(__nv_bfloat162*)(g_P1h + o + 2) = __nv_bfloat162(h2, h3);
    *(__nv_bfloat162*)(g_P1l + o)     = __nv_bfloat162(lo0, lo1);
    *(__nv_bfloat162*)(g_P1l + o + 2) = __nv_bfloat162(lo2, lo3);
}

// ---------------- softmax over d (axis -2): g_S -> P2t hi/lo (transposed) ----
__global__ void softmax_q2d_kernel(const int* __restrict__ qm,
                                   const int* __restrict__ dmk) {
    __shared__ float sm[8][32], ss[8][32], sM[32], sI[32];
    __shared__ float tile[32][33];
    int b = blockIdx.y;
    int tx = threadIdx.x, ty = threadIdx.y;
    int q = blockIdx.x * 32 + tx;
    int qmv = qm[b * QQ + q];
    const float* base = g_S + (size_t)b * DD * QQ + q;
    float m = -1e30f, s = 0.f;
    for (int d = ty; d < DD; d += 8) {
        int mk = (qmv > 0) && (dmk[b * DD + d] > 0);
        float v = mk ? base[(size_t)d * QQ] : -1e30f;
        float nm = fmaxf(m, v);
        s = s * __expf(m - nm) + __expf(v - nm);
        m = nm;
    }
    sm[ty][tx] = m; ss[ty][tx] = s;
    __syncthreads();
    if (ty == 0) {
        float M = -1e30f;
        #pragma unroll
        for (int j = 0; j < 8; j++) M = fmaxf(M, sm[j][tx]);
        float S = 0.f;
        #pragma unroll
        for (int j = 0; j < 8; j++) S += ss[j][tx] * __expf(sm[j][tx] - M);
        sM[tx] = M; sI[tx] = 1.f / S;
    }
    __syncthreads();
    float M = sM[tx], inv = sI[tx];
    int tid = ty * 32 + tx;
    int qr = tid >> 3, seg = (tid & 7) * 4;
    size_t drow = (size_t)b * QQ * DD + (size_t)(blockIdx.x * 32 + qr) * DD;
    for (int d0 = 0; d0 < DD; d0 += 32) {
        #pragma unroll
        for (int dj = ty; dj < 32; dj += 8) {
            int d = d0 + dj;
            int mk = (qmv > 0) && (dmk[b * DD + d] > 0);
            float v = base[(size_t)d * QQ];
            tile[tx][dj] = mk ? __expf(v - M) * inv : 0.f;
        }
        __syncthreads();
        float p0 = tile[qr][seg], p1 = tile[qr][seg + 1];
        float p2 = tile[qr][seg + 2], p3 = tile[qr][seg + 3];
        __nv_bfloat16 h0, l0, h1, l1, h2, l2, h3, l3;
        bsplit(p0, h0, l0); bsplit(p1, h1, l1);
        bsplit(p2, h2, l2); bsplit(p3, h3, l3);
        size_t o = drow + d0 + seg;
        *(__nv_bfloat162*)(g_P2th + o)     = __nv_bfloat162(h0, h1);
        *(__nv_bfloat162*)(g_P2th + o + 2) = __nv_bfloat162(h2, h3);
        *(__nv_bfloat162*)(g_P2tl + o)     = __nv_bfloat162(l0, l1);
        *(__nv_bfloat162*)(g_P2tl + o + 2) = __nv_bfloat162(l2, l3);
        __syncthreads();
    }
}

// ---------------------------------------------------------------------------
extern "C" void kernel_launch(void* const* d_in, const int* in_sizes, int n_in,
                              void* d_out, int out_size) {
    const float* Ud  = (const float*)d_in[0];
    const float* Uq  = (const float*)d_in[1];
    const float* wcw = (const float*)d_in[2];
    const float* wcb = (const float*)d_in[3];
    const int*   qm  = (const int*)d_in[4];
    const int*   dmk = (const int*)d_in[5];
    float* out = (float*)d_out;

    // pre-split conversions (+ transposes, + wdot folding into Uq)
    conv_ud_kernel<<<dim3(HH / 32, DD / 32, BB), dim3(32, 8)>>>(Ud);
    conv_uq_kernel<<<dim3(HH / 32, QQ / 32, BB), dim3(32, 8)>>>(Uq, wcw + 2 * HH);

    // s_d, s_q
    rowdot_kernel<<<(BB * DD) / 8, 256>>>(Ud, wcw, BB * DD, 0);
    rowdot_kernel<<<(BB * QQ) / 8, 256>>>(Uq, wcw + HH, BB * QQ, 1);

    // logits
    gemm1_mma<<<dim3(DD / 128, BB), 256>>>(wcb);

    // softmaxes (emit bf16 hi/lo directly)
    softmax_d2q_kernel<<<(BB * DD) / 8, 256>>>(qm, dmk);
    softmax_q2d_kernel<<<dim3(QQ / 32, BB), dim3(32, 8)>>>(qm, dmk);

    // Tt = (P2^T @ Ud)^T  (bf16 split epilogue)
    gemm3_mma<<<dim3(HH / 128, BB), 256>>>();

    // A_d2q (slices 0,1,2) and A_q2d (slice 3)
    gemm24_mma<<<dim3(HH / 128, DD / 128, BB), 256>>>(Ud, out, 0);
    gemm24_mma<<<dim3(HH / 128, DD / 128, BB), 256>>>(Ud, out, 1);
}

// round 6
// speedup vs baseline: 1.0945x; 1.0945x over previous
#include <cuda_runtime.h>
#include <cuda_bf16.h>
#include <cstdint>

#define BB 16
#define DD 1024
#define QQ 128
#define HH 1024

// ---------------- scratch (device globals) ----------------------------------
__device__ float g_S [BB * DD * QQ];
__device__ float g_sd[BB * DD];
__device__ float g_sq[BB * QQ];
// pre-split bf16 hi/lo operand arrays
__device__ __nv_bfloat16 g_Udh [BB * DD * HH], g_Udl [BB * DD * HH];  // Ud  [b,d,h]
__device__ __nv_bfloat16 g_Udth[BB * HH * DD], g_Udtl[BB * HH * DD];  // Ud^T [b,h,d]
__device__ __nv_bfloat16 g_Uqwh[BB * QQ * HH], g_Uqwl[BB * QQ * HH];  // Uq*wdot [b,q,h]
__device__ __nv_bfloat16 g_Uqth[BB * HH * QQ], g_Uqtl[BB * HH * QQ];  // Uq^T [b,h,q]
__device__ __nv_bfloat16 g_P1h [BB * DD * QQ], g_P1l [BB * DD * QQ];  // S_d2q [b,d,q]
__device__ __nv_bfloat16 g_P2th[BB * QQ * DD], g_P2tl[BB * QQ * DD];  // S_q2d^T [b,q,d]
__device__ __nv_bfloat16 g_Tth [BB * HH * QQ], g_Ttl [BB * HH * QQ];  // T^T [b,h,q]

// ---------------- helpers ----------------------------------------------------
__device__ __forceinline__ uint32_t smem_u32(const void* p) {
    uint32_t a;
    asm("{ .reg .u64 t; cvta.to.shared.u64 t, %1; cvt.u32.u64 %0, t; }" : "=r"(a) : "l"(p));
    return a;
}
__device__ __forceinline__ uint32_t L32(const __nv_bfloat16* p) {
    return *(const uint32_t*)p;
}
__device__ __forceinline__ void mma_bf16(float* c, const uint32_t* a, const uint32_t* b) {
    asm volatile(
        "mma.sync.aligned.m16n8k16.row.col.f32.bf16.bf16.f32 "
        "{%0,%1,%2,%3}, {%4,%5,%6,%7}, {%8,%9}, {%0,%1,%2,%3};"
        : "+f"(c[0]), "+f"(c[1]), "+f"(c[2]), "+f"(c[3])
        : "r"(a[0]), "r"(a[1]), "r"(a[2]), "r"(a[3]), "r"(b[0]), "r"(b[1]));
}
__device__ __forceinline__ void bsplit(float x, __nv_bfloat16& h, __nv_bfloat16& l) {
    h = __float2bfloat16(x);
    l = __float2bfloat16(x - __bfloat162float(h));
}
#define CPA16(sa, g) \
    asm volatile("cp.async.cg.shared.global [%0], [%1], 16;" :: "r"(sa), "l"(g))
#define CPA_COMMIT() asm volatile("cp.async.commit_group;" ::: "memory")
#define CPA_WAIT0()  asm volatile("cp.async.wait_group 0;" ::: "memory")

// one k16 step on 128x128 tile; 3 precision passes; optional second B operand.
template <int ST, bool DUAL>
__device__ __forceinline__ void k16_step(
    const __nv_bfloat16* sAh, const __nv_bfloat16* sAl,
    const __nv_bfloat16* sBh, const __nv_bfloat16* sBl,
    const __nv_bfloat16* sCh, const __nv_bfloat16* sCl,
    int kb, int wm, int wn, int gr, int qp,
    float (&acc)[4][4][4], float (&accB)[4][4][4])
{
    uint32_t ah[4][4], al[4][4];
    #pragma unroll
    for (int i = 0; i < 4; i++) {
        int r = wm * 64 + i * 16 + gr;
        const __nv_bfloat16* p = sAh + r * ST + kb + 2 * qp;
        const __nv_bfloat16* q = sAl + r * ST + kb + 2 * qp;
        ah[i][0] = L32(p);     ah[i][1] = L32(p + 8 * ST);
        ah[i][2] = L32(p + 8); ah[i][3] = L32(p + 8 * ST + 8);
        al[i][0] = L32(q);     al[i][1] = L32(q + 8 * ST);
        al[i][2] = L32(q + 8); al[i][3] = L32(q + 8 * ST + 8);
    }
    {
        uint32_t bh[4][2], bl[4][2];
        #pragma unroll
        for (int j = 0; j < 4; j++) {
            int c = wn * 32 + j * 8 + gr;
            const __nv_bfloat16* p = sBh + c * ST + kb + 2 * qp;
            const __nv_bfloat16* q = sBl + c * ST + kb + 2 * qp;
            bh[j][0] = L32(p); bh[j][1] = L32(p + 8);
            bl[j][0] = L32(q); bl[j][1] = L32(q + 8);
        }
        #pragma unroll
        for (int i = 0; i < 4; i++)
            #pragma unroll
            for (int j = 0; j < 4; j++) mma_bf16(acc[i][j], ah[i], bh[j]);
        #pragma unroll
        for (int i = 0; i < 4; i++)
            #pragma unroll
            for (int j = 0; j < 4; j++) mma_bf16(acc[i][j], ah[i], bl[j]);
        #pragma unroll
        for (int i = 0; i < 4; i++)
            #pragma unroll
            for (int j = 0; j < 4; j++) mma_bf16(acc[i][j], al[i], bh[j]);
    }
    if (DUAL) {
        uint32_t bh[4][2], bl[4][2];
        #pragma unroll
        for (int j = 0; j < 4; j++) {
            int c = wn * 32 + j * 8 + gr;
            const __nv_bfloat16* p = sCh + c * ST + kb + 2 * qp;
            const __nv_bfloat16* q = sCl + c * ST + kb + 2 * qp;
            bh[j][0] = L32(p); bh[j][1] = L32(p + 8);
            bl[j][0] = L32(q); bl[j][1] = L32(q + 8);
        }
        #pragma unroll
        for (int i = 0; i < 4; i++)
            #pragma unroll
            for (int j = 0; j < 4; j++) mma_bf16(accB[i][j], ah[i], bh[j]);
        #pragma unroll
        for (int i = 0; i < 4; i++)
            #pragma unroll
            for (int j = 0; j < 4; j++) mma_bf16(accB[i][j], ah[i], bl[j]);
        #pragma unroll
        for (int i = 0; i < 4; i++)
            #pragma unroll
            for (int j = 0; j < 4; j++) mma_bf16(accB[i][j], al[i], bh[j]);
    }
}

// cp.async one k32 stage (4 arrays of 128x32 bf16, row stride 80 B in smem)
__device__ __forceinline__ void cpa_stage32(
    uint32_t sbuf,
    const __nv_bfloat16* Ah, const __nv_bfloat16* Al,
    const __nv_bfloat16* Bh, const __nv_bfloat16* Bl,
    int lda, int ldb, int k0, int srow, int srow2, int kc)
{
    CPA16(sbuf +         srow  * 80 + kc * 2, Ah + (size_t)srow  * lda + k0 + kc);
    CPA16(sbuf +         srow2 * 80 + kc * 2, Ah + (size_t)srow2 * lda + k0 + kc);
    CPA16(sbuf + 10240 + srow  * 80 + kc * 2, Al + (size_t)srow  * lda + k0 + kc);
    CPA16(sbuf + 10240 + srow2 * 80 + kc * 2, Al + (size_t)srow2 * lda + k0 + kc);
    CPA16(sbuf + 20480 + srow  * 80 + kc * 2, Bh + (size_t)srow  * ldb + k0 + kc);
    CPA16(sbuf + 20480 + srow2 * 80 + kc * 2, Bh + (size_t)srow2 * ldb + k0 + kc);
    CPA16(sbuf + 30720 + srow  * 80 + kc * 2, Bl + (size_t)srow  * ldb + k0 + kc);
    CPA16(sbuf + 30720 + srow2 * 80 + kc * 2, Bl + (size_t)srow2 * ldb + k0 + kc);
    CPA_COMMIT();
}

#define GEMM_IDS                                                              \
    int t = threadIdx.x;                                                      \
    int wid = t >> 5, lane = t & 31;                                          \
    int wm = wid >> 2, wn = wid & 3;                                          \
    int gr = lane >> 2, qp = lane & 3;                                        \
    int srow = t >> 2, srow2 = (t >> 2) + 64, kc = (t & 3) * 8;

#define ACC_INIT(A)                                                           \
    _Pragma("unroll")                                                         \
    for (int i = 0; i < 4; i++)                                               \
        _Pragma("unroll")                                                     \
        for (int j = 0; j < 4; j++)                                           \
            _Pragma("unroll")                                                 \
            for (int e = 0; e < 4; e++) (A)[i][j][e] = 0.f;

// ---------------- conversion kernels ----------------------------------------
__global__ void conv_ud_kernel(const float* __restrict__ Ud) {
    __shared__ float tile[32][33];
    int b = blockIdx.z, h0 = blockIdx.x * 32, d0 = blockIdx.y * 32;
    int tx = threadIdx.x, ty = threadIdx.y;
    const float* src = Ud + (size_t)b * DD * HH;
    for (int i = ty; i < 32; i += 8) {
        float v = src[(size_t)(d0 + i) * HH + h0 + tx];
        tile[i][tx] = v;
        __nv_bfloat16 h, l; bsplit(v, h, l);
        size_t o = (size_t)b * DD * HH + (size_t)(d0 + i) * HH + h0 + tx;
        g_Udh[o] = h; g_Udl[o] = l;
    }
    __syncthreads();
    for (int i = ty; i < 32; i += 8) {
        float v = tile[tx][i];
        __nv_bfloat16 h, l; bsplit(v, h, l);
        size_t o = (size_t)b * HH * DD + (size_t)(h0 + i) * DD + d0 + tx;
        g_Udth[o] = h; g_Udtl[o] = l;
    }
}

__global__ void conv_uq_kernel(const float* __restrict__ Uq,
                               const float* __restrict__ wdot) {
    __shared__ float tile[32][33];
    int b = blockIdx.z, h0 = blockIdx.x * 32, q0 = blockIdx.y * 32;
    int tx = threadIdx.x, ty = threadIdx.y;
    const float* src = Uq + (size_t)b * QQ * HH;
    float w = wdot[h0 + tx];
    for (int i = ty; i < 32; i += 8) {
        float v = src[(size_t)(q0 + i) * HH + h0 + tx];
        tile[i][tx] = v;
        __nv_bfloat16 h, l; bsplit(v * w, h, l);
        size_t o = (size_t)b * QQ * HH + (size_t)(q0 + i) * HH + h0 + tx;
        g_Uqwh[o] = h; g_Uqwl[o] = l;
    }
    __syncthreads();
    for (int i = ty; i < 32; i += 8) {
        float v = tile[tx][i];
        __nv_bfloat16 h, l; bsplit(v, h, l);
        size_t o = (size_t)b * HH * QQ + (size_t)(h0 + i) * QQ + q0 + tx;
        g_Uqth[o] = h; g_Uqtl[o] = l;
    }
}

// ---------------- row dots ---------------------------------------------------
__global__ void rowdot_kernel(const float* __restrict__ X,
                              const float* __restrict__ w, int nrows, int mode) {
    int gw = (blockIdx.x * blockDim.x + threadIdx.x) >> 5;
    int lane = threadIdx.x & 31;
    if (gw >= nrows) return;
    const float* row = X + (size_t)gw * HH;
    float s = 0.f;
    #pragma unroll
    for (int k = lane * 4; k < HH; k += 128) {
        float4 v = *(const float4*)(row + k);
        float4 ww = *(const float4*)(w + k);
        s += v.x * ww.x + v.y * ww.y + v.z * ww.z + v.w * ww.w;
    }
    #pragma unroll
    for (int o = 16; o; o >>= 1) s += __shfl_xor_sync(0xffffffffu, s, o);
    if (lane == 0) { if (mode == 0) g_sd[gw] = s; else g_sq[gw] = s; }
}

// ---------------- GEMM1: S = Ud @ (Uq*wdot)^T + sd + sq + bias ---------------
// cp.async double-buffered. dyn smem = 2 stages x 40960 B.
__global__ __launch_bounds__(256) void gemm1_mma(const float* __restrict__ wcb) {
    extern __shared__ __nv_bfloat16 dyn[];
    GEMM_IDS
    int b = blockIdx.y, m0 = blockIdx.x * 128;
    const __nv_bfloat16* Ah = g_Udh + (size_t)b * DD * HH + (size_t)m0 * HH;
    const __nv_bfloat16* Al = g_Udl + (size_t)b * DD * HH + (size_t)m0 * HH;
    const __nv_bfloat16* Bh = g_Uqwh + (size_t)b * QQ * HH;
    const __nv_bfloat16* Bl = g_Uqwl + (size_t)b * QQ * HH;
    float acc[4][4][4];
    ACC_INIT(acc)
    uint32_t sb = smem_u32(dyn);

    cpa_stage32(sb, Ah, Al, Bh, Bl, HH, HH, 0, srow, srow2, kc);
    for (int it = 0; it < HH / 32; it++) {
        CPA_WAIT0();
        __syncthreads();
        if (it + 1 < HH / 32)
            cpa_stage32(sb + ((it + 1) & 1) * 40960, Ah, Al, Bh, Bl, HH, HH,
                        (it + 1) * 32, srow, srow2, kc);
        const __nv_bfloat16* cA = dyn + (it & 1) * 20480;
        k16_step<40, false>(cA, cA + 5120, cA + 10240, cA + 15360,
                            nullptr, nullptr, 0, wm, wn, gr, qp, acc, acc);
        k16_step<40, false>(cA, cA + 5120, cA + 10240, cA + 15360,
                            nullptr, nullptr, 16, wm, wn, gr, qp, acc, acc);
    }

    float bias = wcb[0];
    #pragma unroll
    for (int i = 0; i < 4; i++) {
        int m = m0 + wm * 64 + i * 16 + gr;
        float sd0 = g_sd[b * DD + m] + bias;
        float sd1 = g_sd[b * DD + m + 8] + bias;
        #pragma unroll
        for (int j = 0; j < 4; j++) {
            int n = wn * 32 + j * 8 + 2 * qp;
            float sq0 = g_sq[b * QQ + n], sq1 = g_sq[b * QQ + n + 1];
            float* d0 = g_S + ((size_t)b * DD + m) * QQ + n;
            float* d1 = g_S + ((size_t)b * DD + m + 8) * QQ + n;
            *(float2*)d0 = make_float2(acc[i][j][0] + sd0 + sq0, acc[i][j][1] + sd0 + sq1);
            *(float2*)d1 = make_float2(acc[i][j][2] + sd1 + sq0, acc[i][j][3] + sd1 + sq1);
        }
    }
}

// ---------------- GEMM3: Tt[h,q] = sum_d Udt[h,d]*P2t[q,d] -> bf16 split -----
__global__ __launch_bounds__(256) void gemm3_mma() {
    extern __shared__ __nv_bfloat16 dyn[];
    GEMM_IDS
    int b = blockIdx.y, m0 = blockIdx.x * 128;
    const __nv_bfloat16* Ah = g_Udth + (size_t)b * HH * DD + (size_t)m0 * DD;
    const __nv_bfloat16* Al = g_Udtl + (size_t)b * HH * DD + (size_t)m0 * DD;
    const __nv_bfloat16* Bh = g_P2th + (size_t)b * QQ * DD;
    const __nv_bfloat16* Bl = g_P2tl + (size_t)b * QQ * DD;
    float acc[4][4][4];
    ACC_INIT(acc)
    uint32_t sb = smem_u32(dyn);

    cpa_stage32(sb, Ah, Al, Bh, Bl, DD, DD, 0, srow, srow2, kc);
    for (int it = 0; it < DD / 32; it++) {
        CPA_WAIT0();
        __syncthreads();
        if (it + 1 < DD / 32)
            cpa_stage32(sb + ((it + 1) & 1) * 40960, Ah, Al, Bh, Bl, DD, DD,
                        (it + 1) * 32, srow, srow2, kc);
        const __nv_bfloat16* cA = dyn + (it & 1) * 20480;
        k16_step<40, false>(cA, cA + 5120, cA + 10240, cA + 15360,
                            nullptr, nullptr, 0, wm, wn, gr, qp, acc, acc);
        k16_step<40, false>(cA, cA + 5120, cA + 10240, cA + 15360,
                            nullptr, nullptr, 16, wm, wn, gr, qp, acc, acc);
    }

    #pragma unroll
    for (int i = 0; i < 4; i++) {
        int m = m0 + wm * 64 + i * 16 + gr;
        #pragma unroll
        for (int j = 0; j < 4; j++) {
            int n = wn * 32 + j * 8 + 2 * qp;
            #pragma unroll
            for (int rr = 0; rr < 2; rr++) {
                float a0 = acc[i][j][2 * rr], a1 = acc[i][j][2 * rr + 1];
                __nv_bfloat16 h0, l0, h1, l1;
                bsplit(a0, h0, l0); bsplit(a1, h1, l1);
                size_t o = ((size_t)b * HH + m + rr * 8) * QQ + n;
                *(__nv_bfloat162*)(g_Tth + o) = __nv_bfloat162(h0, h1);
                *(__nv_bfloat162*)(g_Ttl + o) = __nv_bfloat162(l0, l1);
            }
        }
    }
}

// ---------------- fused GEMM2+4: one pass, K=128 entirely in smem ------------
// C2[d,h] = sum_q P1[d,q]*Uqt[h,q]; C4[d,h] = sum_q P1[d,q]*Tt[h,q]
// writes all 4 output slices. dyn smem = 6 tiles x 34816 B = 208896 B.
#define ST24 136
#define TSZ  (128 * ST24)   // elems per tile
__global__ __launch_bounds__(256) void gemm24f_mma(
    const float* __restrict__ Ud, float* __restrict__ out) {
    extern __shared__ __nv_bfloat16 dyn[];
    GEMM_IDS
    (void)srow; (void)srow2; (void)kc;
    int b = blockIdx.z, n0 = blockIdx.x * 128, m0 = blockIdx.y * 128;
    const __nv_bfloat16* srcs[6];
    srcs[0] = g_P1h  + (size_t)b * DD * QQ + (size_t)m0 * QQ;
    srcs[1] = g_P1l  + (size_t)b * DD * QQ + (size_t)m0 * QQ;
    srcs[2] = g_Uqth + (size_t)b * HH * QQ + (size_t)n0 * QQ;
    srcs[3] = g_Uqtl + (size_t)b * HH * QQ + (size_t)n0 * QQ;
    srcs[4] = g_Tth  + (size_t)b * HH * QQ + (size_t)n0 * QQ;
    srcs[5] = g_Ttl  + (size_t)b * HH * QQ + (size_t)n0 * QQ;

    uint32_t sb = smem_u32(dyn);
    // load all 6 tiles (128x128 bf16) via cp.async
    #pragma unroll
    for (int v = 0; v < 8; v++) {
        int c = v * 256 + t;
        int row = c >> 4, kb = (c & 15) * 8;
        #pragma unroll
        for (int s = 0; s < 6; s++)
            CPA16(sb + s * (TSZ * 2) + row * (ST24 * 2) + kb * 2,
                  srcs[s] + (size_t)row * QQ + kb);
    }
    CPA_COMMIT();
    CPA_WAIT0();
    __syncthreads();

    float acc2[4][4][4], acc4[4][4][4];
    ACC_INIT(acc2)
    ACC_INIT(acc4)
    const __nv_bfloat16* pA = dyn;
    #pragma unroll
    for (int s = 0; s < 8; s++)
        k16_step<ST24, true>(pA, pA + TSZ, pA + 2 * TSZ, pA + 3 * TSZ,
                             pA + 4 * TSZ, pA + 5 * TSZ,
                             s * 16, wm, wn, gr, qp, acc2, acc4);

    #pragma unroll
    for (int i = 0; i < 4; i++) {
        int m = m0 + wm * 64 + i * 16 + gr;
        #pragma unroll
        for (int j = 0; j < 4; j++) {
            int n = n0 + wn * 32 + j * 8 + 2 * qp;
            #pragma unroll
            for (int rr = 0; rr < 2; rr++) {
                int mm = m + rr * 8;
                float a2x = acc2[i][j][2 * rr], a2y = acc2[i][j][2 * rr + 1];
                float a4x = acc4[i][j][2 * rr], a4y = acc4[i][j][2 * rr + 1];
                float2 u = *(const float2*)(Ud + ((size_t)b * DD + mm) * HH + n);
                float* ob = out + ((size_t)b * DD + mm) * (size_t)(4 * HH) + n;
                *(float2*)(ob)          = u;
                *(float2*)(ob + HH)     = make_float2(a2x, a2y);
                *(float2*)(ob + 2 * HH) = make_float2(u.x * a2x, u.y * a2y);
                *(float2*)(ob + 3 * HH) = make_float2(u.x * a4x, u.y * a4y);
            }
        }
    }
}

// ---------------- softmax over q (axis -1): g_S -> P1 hi/lo ------------------
__global__ void softmax_d2q_kernel(const int* __restrict__ qm,
                                   const int* __restrict__ dmk) {
    int row = (blockIdx.x * blockDim.x + threadIdx.x) >> 5;
    if (row >= BB * DD) return;
    int lane = threadIdx.x & 31;
    int b = row >> 10;
    int dmv = dmk[row];
    const float* src = g_S + (size_t)row * QQ;
    float4 v = *(const float4*)(src + lane * 4);
    int4 q4 = *(const int4*)(qm + b * QQ + lane * 4);
    int mk0 = (dmv > 0) && (q4.x > 0), mk1 = (dmv > 0) && (q4.y > 0);
    int mk2 = (dmv > 0) && (q4.z > 0), mk3 = (dmv > 0) && (q4.w > 0);
    float l0 = mk0 ? v.x : -1e30f, l1 = mk1 ? v.y : -1e30f;
    float l2 = mk2 ? v.z : -1e30f, l3 = mk3 ? v.w : -1e30f;
    float mx = fmaxf(fmaxf(l0, l1), fmaxf(l2, l3));
    #pragma unroll
    for (int o = 16; o; o >>= 1) mx = fmaxf(mx, __shfl_xor_sync(0xffffffffu, mx, o));
    float e0 = __expf(l0 - mx), e1 = __expf(l1 - mx);
    float e2 = __expf(l2 - mx), e3 = __expf(l3 - mx);
    float s = e0 + e1 + e2 + e3;
    #pragma unroll
    for (int o = 16; o; o >>= 1) s += __shfl_xor_sync(0xffffffffu, s, o);
    float inv = 1.f / s;
    float p0 = mk0 ? e0 * inv : 0.f, p1 = mk1 ? e1 * inv : 0.f;
    float p2 = mk2 ? e2 * inv : 0.f, p3 = mk3 ? e3 * inv : 0.f;
    __nv_bfloat16 h0, lo0, h1, lo1, h2, lo2, h3, lo3;
    bsplit(p0, h0, lo0); bsplit(p1, h1, lo1);
    bsplit(p2, h2, lo2); bsplit(p3, h3, lo3);
    size_t o = (size_t)row * QQ + lane * 4;
    *(__nv_bfloat162*)(g_P1h + o)     = __nv_bfloat162(h0, h1);
    *(__nv_bfloat162*)(g_P1h + o + 2) = __nv_bfloat162(h2, h3);
    *(__nv_bfloat162*)(g_P1l + o)     = __nv_bfloat162(lo0, lo1);
    *(__nv_bfloat162*)(g_P1l + o + 2) = __nv_bfloat162(lo2, lo3);
}

// ---------------- softmax over d (axis -2): g_S -> P2t hi/lo (transposed) ----
__global__ void softmax_q2d_kernel(const int* __restrict__ qm,
                                   const int* __restrict__ dmk) {
    __shared__ float sm[8][32], ss[8][32], sM[32], sI[32];
    __shared__ float tile[32][33];
    int b = blockIdx.y;
    int tx = threadIdx.x, ty = threadIdx.y;
    int q = blockIdx.x * 32 + tx;
    int qmv = qm[b * QQ + q];
    const float* base = g_S + (size_t)b * DD * QQ + q;
    float m = -1e30f, s = 0.f;
    for (int d = ty; d < DD; d += 8) {
        int mk = (qmv > 0) && (dmk[b * DD + d] > 0);
        float v = mk ? base[(size_t)d * QQ] : -1e30f;
        float nm = fmaxf(m, v);
        s = s * __expf(m - nm) + __expf(v - nm);
        m = nm;
    }
    sm[ty][tx] = m; ss[ty][tx] = s;
    __syncthreads();
    if (ty == 0) {
        float M = -1e30f;
        #pragma unroll
        for (int j = 0; j < 8; j++) M = fmaxf(M, sm[j][tx]);
        float S = 0.f;
        #pragma unroll
        for (int j = 0; j < 8; j++) S += ss[j][tx] * __expf(sm[j][tx] - M);
        sM[tx] = M; sI[tx] = 1.f / S;
    }
    __syncthreads();
    float M = sM[tx], inv = sI[tx];
    int tid = ty * 32 + tx;
    int qr = tid >> 3, seg = (tid & 7) * 4;
    size_t drow = (size_t)b * QQ * DD + (size_t)(blockIdx.x * 32 + qr) * DD;
    for (int d0 = 0; d0 < DD; d0 += 32) {
        #pragma unroll
        for (int dj = ty; dj < 32; dj += 8) {
            int d = d0 + dj;
            int mk = (qmv > 0) && (dmk[b * DD + d] > 0);
            float v = base[(size_t)d * QQ];
            tile[tx][dj] = mk ? __expf(v - M) * inv : 0.f;
        }
        __syncthreads();
        float p0 = tile[qr][seg], p1 = tile[qr][seg + 1];
        float p2 = tile[qr][seg + 2], p3 = tile[qr][seg + 3];
        __nv_bfloat16 h0, l0, h1, l1, h2, l2, h3, l3;
        bsplit(p0, h0, l0); bsplit(p1, h1, l1);
        bsplit(p2, h2, l2); bsplit(p3, h3, l3);
        size_t o = drow + d0 + seg;
        *(__nv_bfloat162*)(g_P2th + o)     = __nv_bfloat162(h0, h1);
        *(__nv_bfloat162*)(g_P2th + o + 2) = __nv_bfloat162(h2, h3);
        *(__nv_bfloat162*)(g_P2tl + o)     = __nv_bfloat162(l0, l1);
        *(__nv_bfloat162*)(g_P2tl + o + 2) = __nv_bfloat162(l2, l3);
        __syncthreads();
    }
}

// ---------------------------------------------------------------------------
extern "C" void kernel_launch(void* const* d_in, const int* in_sizes, int n_in,
                              void* d_out, int out_size) {
    const float* Ud  = (const float*)d_in[0];
    const float* Uq  = (const float*)d_in[1];
    const float* wcw = (const float*)d_in[2];
    const float* wcb = (const float*)d_in[3];
    const int*   qm  = (const int*)d_in[4];
    const int*   dmk = (const int*)d_in[5];
    float* out = (float*)d_out;

    cudaFuncSetAttribute(gemm1_mma,   cudaFuncAttributeMaxDynamicSharedMemorySize, 81920);
    cudaFuncSetAttribute(gemm3_mma,   cudaFuncAttributeMaxDynamicSharedMemorySize, 81920);
    cudaFuncSetAttribute(gemm24f_mma, cudaFuncAttributeMaxDynamicSharedMemorySize, 208896);

    // pre-split conversions (+ transposes, + wdot folding into Uq)
    conv_ud_kernel<<<dim3(HH / 32, DD / 32, BB), dim3(32, 8)>>>(Ud);
    conv_uq_kernel<<<dim3(HH / 32, QQ / 32, BB), dim3(32, 8)>>>(Uq, wcw + 2 * HH);

    // s_d, s_q
    rowdot_kernel<<<(BB * DD) / 8, 256>>>(Ud, wcw, BB * DD, 0);
    rowdot_kernel<<<(BB * QQ) / 8, 256>>>(Uq, wcw + HH, BB * QQ, 1);

    // logits
    gemm1_mma<<<dim3(DD / 128, BB), 256, 81920>>>(wcb);

    // softmaxes (emit bf16 hi/lo directly)
    softmax_d2q_kernel<<<(BB * DD) / 8, 256>>>(qm, dmk);
    softmax_q2d_kernel<<<dim3(QQ / 32, BB), dim3(32, 8)>>>(qm, dmk);

    // Tt = (P2^T @ Ud)^T  (bf16 split epilogue)
    gemm3_mma<<<dim3(HH / 128, BB), 256, 81920>>>();

    // fused A_d2q + A_q2d, all 4 output slices
    gemm24f_mma<<<dim3(HH / 128, DD / 128, BB), 256, 208896>>>(Ud, out);
}

// round 8
// speedup vs baseline: 1.1538x; 1.0542x over previous
#include <cuda_runtime.h>
#include <cuda_bf16.h>
#include <cstdint>

#define BB 16
#define DD 1024
#define QQ 128
#define HH 1024

// ---------------- scratch (device globals) ----------------------------------
__device__ float g_S [BB * DD * QQ];
__device__ float g_sd[BB * DD];
__device__ float g_sq[BB * QQ];
__device__ float g_cmax[BB * 8 * 128];   // per (b, m-block, q) column partial max
__device__ float g_csum[BB * 8 * 128];   // per (b, m-block, q) column partial sumexp
// pre-split bf16 hi/lo operand arrays
__device__ __nv_bfloat16 g_Udth[BB * HH * DD], g_Udtl[BB * HH * DD];  // Ud^T [b,h,d]
__device__ __nv_bfloat16 g_Uqwh[BB * QQ * HH], g_Uqwl[BB * QQ * HH];  // Uq*wdot [b,q,h]
__device__ __nv_bfloat16 g_Uqth[BB * HH * QQ], g_Uqtl[BB * HH * QQ];  // Uq^T [b,h,q]
__device__ __nv_bfloat16 g_P1h [BB * DD * QQ], g_P1l [BB * DD * QQ];  // S_d2q [b,d,q]
__device__ __nv_bfloat16 g_P2th[BB * QQ * DD], g_P2tl[BB * QQ * DD];  // S_q2d^T [b,q,d]
__device__ __nv_bfloat16 g_Tth [BB * HH * QQ], g_Ttl [BB * HH * QQ];  // T^T [b,h,q]

// ---------------- helpers ----------------------------------------------------
__device__ __forceinline__ uint32_t smem_u32(const void* p) {
    uint32_t a;
    asm("{ .reg .u64 t; cvta.to.shared.u64 t, %1; cvt.u32.u64 %0, t; }" : "=r"(a) : "l"(p));
    return a;
}
__device__ __forceinline__ uint32_t L32(const __nv_bfloat16* p) {
    return *(const uint32_t*)p;
}
__device__ __forceinline__ void mma_bf16(float* c, const uint32_t* a, const uint32_t* b) {
    asm volatile(
        "mma.sync.aligned.m16n8k16.row.col.f32.bf16.bf16.f32 "
        "{%0,%1,%2,%3}, {%4,%5,%6,%7}, {%8,%9}, {%0,%1,%2,%3};"
        : "+f"(c[0]), "+f"(c[1]), "+f"(c[2]), "+f"(c[3])
        : "r"(a[0]), "r"(a[1]), "r"(a[2]), "r"(a[3]), "r"(b[0]), "r"(b[1]));
}
__device__ __forceinline__ void bsplit(float x, __nv_bfloat16& h, __nv_bfloat16& l) {
    h = __float2bfloat16(x);
    l = __float2bfloat16(x - __bfloat162float(h));
}
#define CPA16(sa, g) \
    asm volatile("cp.async.cg.shared.global [%0], [%1], 16;" :: "r"(sa), "l"(g))
#define CPA_COMMIT() asm volatile("cp.async.commit_group;" ::: "memory")
#define CPA_WAIT0()  asm volatile("cp.async.wait_group 0;" ::: "memory")

// one k16 step on 128x128 tile; 3 precision passes; optional second B operand.
template <int ST, bool DUAL>
__device__ __forceinline__ void k16_step(
    const __nv_bfloat16* sAh, const __nv_bfloat16* sAl,
    const __nv_bfloat16* sBh, const __nv_bfloat16* sBl,
    const __nv_bfloat16* sCh, const __nv_bfloat16* sCl,
    int kb, int wm, int wn, int gr, int qp,
    float (&acc)[4][4][4], float (&accB)[4][4][4])
{
    uint32_t ah[4][4], al[4][4];
    #pragma unroll
    for (int i = 0; i < 4; i++) {
        int r = wm * 64 + i * 16 + gr;
        const __nv_bfloat16* p = sAh + r * ST + kb + 2 * qp;
        const __nv_bfloat16* q = sAl + r * ST + kb + 2 * qp;
        ah[i][0] = L32(p);     ah[i][1] = L32(p + 8 * ST);
        ah[i][2] = L32(p + 8); ah[i][3] = L32(p + 8 * ST + 8);
        al[i][0] = L32(q);     al[i][1] = L32(q + 8 * ST);
        al[i][2] = L32(q + 8); al[i][3] = L32(q + 8 * ST + 8);
    }
    {
        uint32_t bh[4][2], bl[4][2];
        #pragma unroll
        for (int j = 0; j < 4; j++) {
            int c = wn * 32 + j * 8 + gr;
            const __nv_bfloat16* p = sBh + c * ST + kb + 2 * qp;
            const __nv_bfloat16* q = sBl + c * ST + kb + 2 * qp;
            bh[j][0] = L32(p); bh[j][1] = L32(p + 8);
            bl[j][0] = L32(q); bl[j][1] = L32(q + 8);
        }
        #pragma unroll
        for (int i = 0; i < 4; i++)
            #pragma unroll
            for (int j = 0; j < 4; j++) mma_bf16(acc[i][j], ah[i], bh[j]);
        #pragma unroll
        for (int i = 0; i < 4; i++)
            #pragma unroll
            for (int j = 0; j < 4; j++) mma_bf16(acc[i][j], ah[i], bl[j]);
        #pragma unroll
        for (int i = 0; i < 4; i++)
            #pragma unroll
            for (int j = 0; j < 4; j++) mma_bf16(acc[i][j], al[i], bh[j]);
    }
    if (DUAL) {
        uint32_t bh[4][2], bl[4][2];
        #pragma unroll
        for (int j = 0; j < 4; j++) {
            int c = wn * 32 + j * 8 + gr;
            const __nv_bfloat16* p = sCh + c * ST + kb + 2 * qp;
            const __nv_bfloat16* q = sCl + c * ST + kb + 2 * qp;
            bh[j][0] = L32(p); bh[j][1] = L32(p + 8);
            bl[j][0] = L32(q); bl[j][1] = L32(q + 8);
        }
        #pragma unroll
        for (int i = 0; i < 4; i++)
            #pragma unroll
            for (int j = 0; j < 4; j++) mma_bf16(accB[i][j], ah[i], bh[j]);
        #pragma unroll
        for (int i = 0; i < 4; i++)
            #pragma unroll
            for (int j = 0; j < 4; j++) mma_bf16(accB[i][j], ah[i], bl[j]);
        #pragma unroll
        for (int i = 0; i < 4; i++)
            #pragma unroll
            for (int j = 0; j < 4; j++) mma_bf16(accB[i][j], al[i], bh[j]);
    }
}

// cp.async one k32 stage (4 arrays of 128x32 bf16, row stride 80 B in smem)
__device__ __forceinline__ void cpa_stage32(
    uint32_t sbuf,
    const __nv_bfloat16* Ah, const __nv_bfloat16* Al,
    const __nv_bfloat16* Bh, const __nv_bfloat16* Bl,
    int lda, int ldb, int k0, int srow, int srow2, int kc)
{
    CPA16(sbuf +         srow  * 80 + kc * 2, Ah + (size_t)srow  * lda + k0 + kc);
    CPA16(sbuf +         srow2 * 80 + kc * 2, Ah + (size_t)srow2 * lda + k0 + kc);
    CPA16(sbuf + 10240 + srow  * 80 + kc * 2, Al + (size_t)srow  * lda + k0 + kc);
    CPA16(sbuf + 10240 + srow2 * 80 + kc * 2, Al + (size_t)srow2 * lda + k0 + kc);
    CPA16(sbuf + 20480 + srow  * 80 + kc * 2, Bh + (size_t)srow  * ldb + k0 + kc);
    CPA16(sbuf + 20480 + srow2 * 80 + kc * 2, Bh + (size_t)srow2 * ldb + k0 + kc);
    CPA16(sbuf + 30720 + srow  * 80 + kc * 2, Bl + (size_t)srow  * ldb + k0 + kc);
    CPA16(sbuf + 30720 + srow2 * 80 + kc * 2, Bl + (size_t)srow2 * ldb + k0 + kc);
    CPA_COMMIT();
}

#define GEMM_IDS                                                              \
    int t = threadIdx.x;                                                      \
    int wid = t >> 5, lane = t & 31;                                          \
    int wm = wid >> 2, wn = wid & 3;                                          \
    int gr = lane >> 2, qp = lane & 3;                                        \
    int srow = t >> 2, srow2 = (t >> 2) + 64, kc = (t & 3) * 8;

#define ACC_INIT(A)                                                           \
    _Pragma("unroll")                                                         \
    for (int i = 0; i < 4; i++)                                               \
        _Pragma("unroll")                                                     \
        for (int j = 0; j < 4; j++)                                           \
            _Pragma("unroll")                                                 \
            for (int e = 0; e < 4; e++) (A)[i][j][e] = 0.f;

// ---------------- conversion kernels ----------------------------------------
// Ud -> transposed split only (Udth/Udtl)
__global__ void conv_ud_kernel(const float* __restrict__ Ud) {
    __shared__ float tile[32][33];
    int b = blockIdx.z, h0 = blockIdx.x * 32, d0 = blockIdx.y * 32;
    int tx = threadIdx.x, ty = threadIdx.y;
    const float* src = Ud + (size_t)b * DD * HH;
    for (int i = ty; i < 32; i += 8)
        tile[i][tx] = src[(size_t)(d0 + i) * HH + h0 + tx];
    __syncthreads();
    for (int i = ty; i < 32; i += 8) {
        float v = tile[tx][i];
        __nv_bfloat16 h, l; bsplit(v, h, l);
        size_t o = (size_t)b * HH * DD + (size_t)(h0 + i) * DD + d0 + tx;
        g_Udth[o] = h; g_Udtl[o] = l;
    }
}

__global__ void conv_uq_kernel(const float* __restrict__ Uq,
                               const float* __restrict__ wdot) {
    __shared__ float tile[32][33];
    int b = blockIdx.z, h0 = blockIdx.x * 32, q0 = blockIdx.y * 32;
    int tx = threadIdx.x, ty = threadIdx.y;
    const float* src = Uq + (size_t)b * QQ * HH;
    float w = wdot[h0 + tx];
    for (int i = ty; i < 32; i += 8) {
        float v = src[(size_t)(q0 + i) * HH + h0 + tx];
        tile[i][tx] = v;
        __nv_bfloat16 h, l; bsplit(v * w, h, l);
        size_t o = (size_t)b * QQ * HH + (size_t)(q0 + i) * HH + h0 + tx;
        g_Uqwh[o] = h; g_Uqwl[o] = l;
    }
    __syncthreads();
    for (int i = ty; i < 32; i += 8) {
        float v = tile[tx][i];
        __nv_bfloat16 h, l; bsplit(v, h, l);
        size_t o = (size_t)b * HH * QQ + (size_t)(h0 + i) * QQ + q0 + tx;
        g_Uqth[o] = h; g_Uqtl[o] = l;
    }
}

// ---------------- row dots ---------------------------------------------------
__global__ void rowdot_kernel(const float* __restrict__ X,
                              const float* __restrict__ w, int nrows, int mode) {
    int gw = (blockIdx.x * blockDim.x + threadIdx.x) >> 5;
    int lane = threadIdx.x & 31;
    if (gw >= nrows) return;
    const float* row = X + (size_t)gw * HH;
    float s = 0.f;
    #pragma unroll
    for (int k = lane * 4; k < HH; k += 128) {
        float4 v = *(const float4*)(row + k);
        float4 ww = *(const float4*)(w + k);
        s += v.x * ww.x + v.y * ww.y + v.z * ww.z + v.w * ww.w;
    }
    #pragma unroll
    for (int o = 16; o; o >>= 1) s += __shfl_xor_sync(0xffffffffu, s, o);
    if (lane == 0) { if (mode == 0) g_sd[gw] = s; else g_sq[gw] = s; }
}

// ---------------- GEMM1 fused: S, P1 (row softmax), column partials ----------
// A = fp32 Ud (register prefetch + split in staging), B = pre-split Uqw.
// dyn smem = 2 stages x (A 20480B + B 20480B) = 81920 B.
__global__ __launch_bounds__(256) void gemm1_mma(
    const float* __restrict__ Ud, const float* __restrict__ wcb,
    const int* __restrict__ qm, const int* __restrict__ dmk) {
    extern __shared__ __nv_bfloat16 dyn[];
    __shared__ float redM[128][4], redS[128][4];
    __shared__ float2 colp[2][128];
    __shared__ int s_qm[128];
    GEMM_IDS
    int b = blockIdx.y, m0 = blockIdx.x * 128;
    const float* A = Ud + (size_t)b * DD * HH + (size_t)m0 * HH;
    const __nv_bfloat16* Bh = g_Uqwh + (size_t)b * QQ * HH;
    const __nv_bfloat16* Bl = g_Uqwl + (size_t)b * QQ * HH;
    float acc[4][4][4];
    ACC_INIT(acc)
    if (t < 128) s_qm[t] = qm[b * QQ + t];
    uint32_t sbB0 = smem_u32(dyn) + 40960;

    float4 pref[4];
    // prologue: A(0) regs + B(0) cp.async
    #pragma unroll
    for (int v = 0; v < 4; v++) {
        int idx = v * 256 + t;
        pref[v] = *(const float4*)(A + (size_t)(idx >> 3) * HH + (idx & 7) * 4);
    }
    CPA16(sbB0 +         srow  * 80 + kc * 2, Bh + (size_t)srow  * HH + kc);
    CPA16(sbB0 +         srow2 * 80 + kc * 2, Bh + (size_t)srow2 * HH + kc);
    CPA16(sbB0 + 10240 + srow  * 80 + kc * 2, Bl + (size_t)srow  * HH + kc);
    CPA16(sbB0 + 10240 + srow2 * 80 + kc * 2, Bl + (size_t)srow2 * HH + kc);
    CPA_COMMIT();

    for (int it = 0; it < HH / 32; it++) {
        CPA_WAIT0();
        // stage A from regs (convert + split)
        __nv_bfloat16* As = dyn + (it & 1) * 10240;
        #pragma unroll
        for (int v = 0; v < 4; v++) {
            int idx = v * 256 + t;
            int row = idx >> 3, cs = (idx & 7) * 4;
            float4 x = pref[v];
            __nv_bfloat16 h0, l0, h1, l1, h2, l2, h3, l3;
            bsplit(x.x, h0, l0); bsplit(x.y, h1, l1);
            bsplit(x.z, h2, l2); bsplit(x.w, h3, l3);
            *(__nv_bfloat162*)(As + row * 40 + cs)            = __nv_bfloat162(h0, h1);
            *(__nv_bfloat162*)(As + row * 40 + cs + 2)        = __nv_bfloat162(h2, h3);
            *(__nv_bfloat162*)(As + 5120 + row * 40 + cs)     = __nv_bfloat162(l0, l1);
            *(__nv_bfloat162*)(As + 5120 + row * 40 + cs + 2) = __nv_bfloat162(l2, l3);
        }
        __syncthreads();
        if (it + 1 < HH / 32) {
            int k0 = (it + 1) * 32;
            uint32_t sbB = sbB0 + ((it + 1) & 1) * 20480;
            CPA16(sbB +         srow  * 80 + kc * 2, Bh + (size_t)srow  * HH + k0 + kc);
            CPA16(sbB +         srow2 * 80 + kc * 2, Bh + (size_t)srow2 * HH + k0 + kc);
            CPA16(sbB + 10240 + srow  * 80 + kc * 2, Bl + (size_t)srow  * HH + k0 + kc);
            CPA16(sbB + 10240 + srow2 * 80 + kc * 2, Bl + (size_t)srow2 * HH + k0 + kc);
            CPA_COMMIT();
            #pragma unroll
            for (int v = 0; v < 4; v++) {
                int idx = v * 256 + t;
                pref[v] = *(const float4*)(A + (size_t)(idx >> 3) * HH + k0 + (idx & 7) * 4);
            }
        }
        const __nv_bfloat16* cA = dyn + (it & 1) * 10240;
        const __nv_bfloat16* cB = dyn + 20480 + (it & 1) * 10240;
        k16_step<40, false>(cA, cA + 5120, cB, cB + 5120,
                            nullptr, nullptr, 0, wm, wn, gr, qp, acc, acc);
        k16_step<40, false>(cA, cA + 5120, cB, cB + 5120,
                            nullptr, nullptr, 16, wm, wn, gr, qp, acc, acc);
    }

    // ---- epilogue: S write + masked logits in acc ----
    float bias = wcb[0];
    float sdv[4][2];
    int dmv[4][2];
    #pragma unroll
    for (int i = 0; i < 4; i++)
        #pragma unroll
        for (int rr = 0; rr < 2; rr++) {
            int m = m0 + wm * 64 + i * 16 + rr * 8 + gr;
            sdv[i][rr] = g_sd[b * DD + m] + bias;
            dmv[i][rr] = dmk[b * DD + m];
        }
    __syncthreads();  // s_qm visible (also separates smem reuse)
    #pragma unroll
    for (int i = 0; i < 4; i++)
        #pragma unroll
        for (int j = 0; j < 4; j++) {
            int n = wn * 32 + j * 8 + 2 * qp;
            float sq0 = g_sq[b * QQ + n], sq1 = g_sq[b * QQ + n + 1];
            int q0 = s_qm[n] > 0, q1 = s_qm[n + 1] > 0;
            #pragma unroll
            for (int rr = 0; rr < 2; rr++) {
                int m = m0 + wm * 64 + i * 16 + rr * 8 + gr;
                float s0 = acc[i][j][2 * rr]     + sdv[i][rr] + sq0;
                float s1 = acc[i][j][2 * rr + 1] + sdv[i][rr] + sq1;
                *(float2*)(g_S + ((size_t)b * DD + m) * QQ + n) = make_float2(s0, s1);
                int dm = dmv[i][rr] > 0;
                acc[i][j][2 * rr]     = (dm && q0) ? s0 : -1e30f;
                acc[i][j][2 * rr + 1] = (dm && q1) ? s1 : -1e30f;
            }
        }

    // ---- row softmax (d2q): max ----
    float M[4][2];
    #pragma unroll
    for (int i = 0; i < 4; i++)
        #pragma unroll
        for (int rr = 0; rr < 2; rr++) {
            float mx = -1e30f;
            #pragma unroll
            for (int j = 0; j < 4; j++)
                mx = fmaxf(mx, fmaxf(acc[i][j][2 * rr], acc[i][j][2 * rr + 1]));
            mx = fmaxf(mx, __shfl_xor_sync(0xffffffffu, mx, 1));
            mx = fmaxf(mx, __shfl_xor_sync(0xffffffffu, mx, 2));
            if (qp == 0) redM[wm * 64 + i * 16 + rr * 8 + gr][wn] = mx;
            M[i][rr] = mx;
        }
    __syncthreads();
    #pragma unroll
    for (int i = 0; i < 4; i++)
        #pragma unroll
        for (int rr = 0; rr < 2; rr++) {
            int r = wm * 64 + i * 16 + rr * 8 + gr;
            M[i][rr] = fmaxf(fmaxf(redM[r][0], redM[r][1]),
                             fmaxf(redM[r][2], redM[r][3]));
        }
    // ---- row softmax: sum ----
    float inv[4][2];
    #pragma unroll
    for (int i = 0; i < 4; i++)
        #pragma unroll
        for (int rr = 0; rr < 2; rr++) {
            float s = 0.f;
            #pragma unroll
            for (int j = 0; j < 4; j++) {
                s += __expf(acc[i][j][2 * rr]     - M[i][rr]);
                s += __expf(acc[i][j][2 * rr + 1] - M[i][rr]);
            }
            s += __shfl_xor_sync(0xffffffffu, s, 1);
            s += __shfl_xor_sync(0xffffffffu, s, 2);
            if (qp == 0) redS[wm * 64 + i * 16 + rr * 8 + gr][wn] = s;
        }
    __syncthreads();
    #pragma unroll
    for (int i = 0; i < 4; i++)
        #pragma unroll
        for (int rr = 0; rr < 2; rr++) {
            int r = wm * 64 + i * 16 + rr * 8 + gr;
            inv[i][rr] = 1.f / (redS[r][0] + redS[r][1] + redS[r][2] + redS[r][3]);
        }
    // ---- write P1 hi/lo ----
    #pragma unroll
    for (int i = 0; i < 4; i++)
        #pragma unroll
        for (int j = 0; j < 4; j++) {
            int n = wn * 32 + j * 8 + 2 * qp;
            int q0 = s_qm[n] > 0, q1 = s_qm[n + 1] > 0;
            #pragma unroll
            for (int rr = 0; rr < 2; rr++) {
                int m = m0 + wm * 64 + i * 16 + rr * 8 + gr;
                int dm = dmv[i][rr] > 0;
                float p0 = (dm && q0) ? __expf(acc[i][j][2 * rr]     - M[i][rr]) * inv[i][rr] : 0.f;
                float p1 = (dm && q1) ? __expf(acc[i][j][2 * rr + 1] - M[i][rr]) * inv[i][rr] : 0.f;
                __nv_bfloat16 h0, l0, h1, l1;
                bsplit(p0, h0, l0); bsplit(p1, h1, l1);
                size_t o = ((size_t)b * DD + m) * QQ + n;
                *(__nv_bfloat162*)(g_P1h + o) = __nv_bfloat162(h0, h1);
                *(__nv_bfloat162*)(g_P1l + o) = __nv_bfloat162(l0, l1);
            }
        }
    // ---- column partials (for q2d) ----
    #pragma unroll
    for (int j = 0; j < 4; j++)
        #pragma unroll
        for (int cc = 0; cc < 2; cc++) {
            float cm = -1e30f;
            #pragma unroll
            for (int i = 0; i < 4; i++)
                #pragma unroll
                for (int rr = 0; rr < 2; rr++)
                    cm = fmaxf(cm, acc[i][j][2 * rr + cc]);
            float cs = 0.f;
            #pragma unroll
            for (int i = 0; i < 4; i++)
                #pragma unroll
                for (int rr = 0; rr < 2; rr++)
                    cs += __expf(acc[i][j][2 * rr + cc] - cm);
            #pragma unroll
            for (int o = 4; o <= 16; o <<= 1) {
                float om = __shfl_xor_sync(0xffffffffu, cm, o);
                float os = __shfl_xor_sync(0xffffffffu, cs, o);
                float nm = fmaxf(cm, om);
                cs = cs * __expf(cm - nm) + os * __expf(om - nm);
                cm = nm;
            }
            if (gr == 0) colp[wm][wn * 32 + j * 8 + 2 * qp + cc] = make_float2(cm, cs);
        }
    __syncthreads();
    if (t < 128) {
        float2 a = colp[0][t], c = colp[1][t];
        float nm = fmaxf(a.x, c.x);
        float s = a.y * __expf(a.x - nm) + c.y * __expf(c.x - nm);
        int idx = (b * 8 + blockIdx.x) * 128 + t;
        g_cmax[idx] = nm; g_csum[idx] = s;
    }
}

// ---------------- GEMM3: Tt[h,q] = sum_d Udt[h,d]*P2t[q,d] -> bf16 split -----
__global__ __launch_bounds__(256) void gemm3_mma() {
    extern __shared__ __nv_bfloat16 dyn[];
    GEMM_IDS
    int b = blockIdx.y, m0 = blockIdx.x * 128;
    const __nv_bfloat16* Ah = g_Udth + (size_t)b * HH * DD + (size_t)m0 * DD;
    const __nv_bfloat16* Al = g_Udtl + (size_t)b * HH * DD + (size_t)m0 * DD;
    const __nv_bfloat16* Bh = g_P2th + (size_t)b * QQ * DD;
    const __nv_bfloat16* Bl = g_P2tl + (size_t)b * QQ * DD;
    float acc[4][4][4];
    ACC_INIT(acc)
    uint32_t sb = smem_u32(dyn);

    cpa_stage32(sb, Ah, Al, Bh, Bl, DD, DD, 0, srow, srow2, kc);
    for (int it = 0; it < DD / 32; it++) {
        CPA_WAIT0();
        __syncthreads();
        if (it + 1 < DD / 32)
            cpa_stage32(sb + ((it + 1) & 1) * 40960, Ah, Al, Bh, Bl, DD, DD,
                        (it + 1) * 32, srow, srow2, kc);
        const __nv_bfloat16* cA = dyn + (it & 1) * 20480;
        k16_step<40, false>(cA, cA + 5120, cA + 10240, cA + 15360,
                            nullptr, nullptr, 0, wm, wn, gr, qp, acc, acc);
        k16_step<40, false>(cA, cA + 5120, cA + 10240, cA + 15360,
                            nullptr, nullptr, 16, wm, wn, gr, qp, acc, acc);
    }

    #pragma unroll
    for (int i = 0; i < 4; i++) {
        int m = m0 + wm * 64 + i * 16 + gr;
        #pragma unroll
        for (int j = 0; j < 4; j++) {
            int n = wn * 32 + j * 8 + 2 * qp;
            #pragma unroll
            for (int rr = 0; rr < 2; rr++) {
                float a0 = acc[i][j][2 * rr], a1 = acc[i][j][2 * rr + 1];
                __nv_bfloat16 h0, l0, h1, l1;
                bsplit(a0, h0, l0); bsplit(a1, h1, l1);
                size_t o = ((size_t)b * HH + m + rr * 8) * QQ + n;
                *(__nv_bfloat162*)(g_Tth + o) = __nv_bfloat162(h0, h1);
                *(__nv_bfloat162*)(g_Ttl + o) = __nv_bfloat162(l0, l1);
            }
        }
    }
}

// ---------------- fused GEMM2+4: one pass, K=128 entirely in smem ------------
#define ST24 136
#define TSZ  (128 * ST24)
__global__ __launch_bounds__(256) void gemm24f_mma(
    const float* __restrict__ Ud, float* __restrict__ out) {
    extern __shared__ __nv_bfloat16 dyn[];
    GEMM_IDS
    (void)srow; (void)srow2; (void)kc;
    int b = blockIdx.z, n0 = blockIdx.x * 128, m0 = blockIdx.y * 128;
    const __nv_bfloat16* srcs[6];
    srcs[0] = g_P1h  + (size_t)b * DD * QQ + (size_t)m0 * QQ;
    srcs[1] = g_P1l  + (size_t)b * DD * QQ + (size_t)m0 * QQ;
    srcs[2] = g_Uqth + (size_t)b * HH * QQ + (size_t)n0 * QQ;
    srcs[3] = g_Uqtl + (size_t)b * HH * QQ + (size_t)n0 * QQ;
    srcs[4] = g_Tth  + (size_t)b * HH * QQ + (size_t)n0 * QQ;
    srcs[5] = g_Ttl  + (size_t)b * HH * QQ + (size_t)n0 * QQ;

    uint32_t sb = smem_u32(dyn);
    #pragma unroll
    for (int v = 0; v < 8; v++) {
        int c = v * 256 + t;
        int row = c >> 4, kb = (c & 15) * 8;
        #pragma unroll
        for (int s = 0; s < 6; s++)
            CPA16(sb + s * (TSZ * 2) + row * (ST24 * 2) + kb * 2,
                  srcs[s] + (size_t)row * QQ + kb);
    }
    CPA_COMMIT();
    CPA_WAIT0();
    __syncthreads();

    float acc2[4][4][4], acc4[4][4][4];
    ACC_INIT(acc2)
    ACC_INIT(acc4)
    const __nv_bfloat16* pA = dyn;
    #pragma unroll
    for (int s = 0; s < 8; s++)
        k16_step<ST24, true>(pA, pA + TSZ, pA + 2 * TSZ, pA + 3 * TSZ,
                             pA + 4 * TSZ, pA + 5 * TSZ,
                             s * 16, wm, wn, gr, qp, acc2, acc4);

    #pragma unroll
    for (int i = 0; i < 4; i++) {
        int m = m0 + wm * 64 + i * 16 + gr;
        #pragma unroll
        for (int j = 0; j < 4; j++) {
            int n = n0 + wn * 32 + j * 8 + 2 * qp;
            #pragma unroll
            for (int rr = 0; rr < 2; rr++) {
                int mm = m + rr * 8;
                float a2x = acc2[i][j][2 * rr], a2y = acc2[i][j][2 * rr + 1];
                float a4x = acc4[i][j][2 * rr], a4y = acc4[i][j][2 * rr + 1];
                float2 u = *(const float2*)(Ud + ((size_t)b * DD + mm) * HH + n);
                float* ob = out + ((size_t)b * DD + mm) * (size_t)(4 * HH) + n;
                *(float2*)(ob)          = u;
                *(float2*)(ob + HH)     = make_float2(a2x, a2y);
                *(float2*)(ob + 2 * HH) = make_float2(u.x * a2x, u.y * a2y);
                *(float2*)(ob + 3 * HH) = make_float2(u.x * a4x, u.y * a4y);
            }
        }
    }
}

// ---------------- single-pass q2d softmax (uses column partials) -------------
__global__ void softmax_q2d_kernel(const int* __restrict__ qm,
                                   const int* __restrict__ dmk) {
    __shared__ float sM[32], sI[32];
    __shared__ float tile[32][33];
    int b = blockIdx.y;
    int tx = threadIdx.x, ty = threadIdx.y;
    int q = blockIdx.x * 32 + tx;
    int qmv = qm[b * QQ + q];
    int tid = ty * 32 + tx;
    if (tid < 32) {
        int qq = blockIdx.x * 32 + tid;
        float m = -1e30f, s = 0.f;
        #pragma unroll
        for (int k = 0; k < 8; k++) {
            float mk = g_cmax[(b * 8 + k) * 128 + qq];
            float sk = g_csum[(b * 8 + k) * 128 + qq];
            float nm = fmaxf(m, mk);
            s = s * __expf(m - nm) + sk * __expf(mk - nm);
            m = nm;
        }
        sM[tid] = m; sI[tid] = 1.f / s;
    }
    __syncthreads();
    float M = sM[tx], inv = sI[tx];
    const float* base = g_S + (size_t)b * DD * QQ + q;
    int qr = tid >> 3, seg = (tid & 7) * 4;
    size_t drow = (size_t)b * QQ * DD + (size_t)(blockIdx.x * 32 + qr) * DD;
    for (int d0 = 0; d0 < DD; d0 += 32) {
        #pragma unroll
        for (int dj = ty; dj < 32; dj += 8) {
            int d = d0 + dj;
            int mk = (qmv > 0) && (dmk[b * DD + d] > 0);
            float v = base[(size_t)d * QQ];
            tile[tx][dj] = mk ? __expf(v - M) * inv : 0.f;
        }
        __syncthreads();
        float p0 = tile[qr][seg], p1 = tile[qr][seg + 1];
        float p2 = tile[qr][seg + 2], p3 = tile[qr][seg + 3];
        __nv_bfloat16 h0, l0, h1, l1, h2, l2, h3, l3;
        bsplit(p0, h0, l0); bsplit(p1, h1, l1);
        bsplit(p2, h2, l2); bsplit(p3, h3, l3);
        size_t o = drow + d0 + seg;
        *(__nv_bfloat162*)(g_P2th + o)     = __nv_bfloat162(h0, h1);
        *(__nv_bfloat162*)(g_P2th + o + 2) = __nv_bfloat162(h2, h3);
        *(__nv_bfloat162*)(g_P2tl + o)     = __nv_bfloat162(l0, l1);
        *(__nv_bfloat162*)(g_P2tl + o + 2) = __nv_bfloat162(l2, l3);
        __syncthreads();
    }
}

// ---------------------------------------------------------------------------
extern "C" void kernel_launch(void* const* d_in, const int* in_sizes, int n_in,
                              void* d_out, int out_size) {
    const float* Ud  = (const float*)d_in[0];
    const float* Uq  = (const float*)d_in[1];
    const float* wcw = (const float*)d_in[2];
    const float* wcb = (const float*)d_in[3];
    const int*   qm  = (const int*)d_in[4];
    const int*   dmk = (const int*)d_in[5];
    float* out = (float*)d_out;

    cudaFuncSetAttribute(gemm1_mma,   cudaFuncAttributeMaxDynamicSharedMemorySize, 81920);
    cudaFuncSetAttribute(gemm3_mma,   cudaFuncAttributeMaxDynamicSharedMemorySize, 81920);
    cudaFuncSetAttribute(gemm24f_mma, cudaFuncAttributeMaxDynamicSharedMemorySize, 208896);

    conv_ud_kernel<<<dim3(HH / 32, DD / 32, BB), dim3(32, 8)>>>(Ud);
    conv_uq_kernel<<<dim3(HH / 32, QQ / 32, BB), dim3(32, 8)>>>(Uq, wcw + 2 * HH);

    rowdot_kernel<<<(BB * DD) / 8, 256>>>(Ud, wcw, BB * DD, 0);
    rowdot_kernel<<<(BB * QQ) / 8, 256>>>(Uq, wcw + HH, BB * QQ, 1);

    // logits + fused row softmax + column partials
    gemm1_mma<<<dim3(DD / 128, BB), 256, 81920>>>(Ud, wcb, qm, dmk);

    // single-pass column softmax -> P2t
    softmax_q2d_kernel<<<dim3(QQ / 32, BB), dim3(32, 8)>>>(qm, dmk);

    // Tt = (P2^T @ Ud)^T
    gemm3_mma<<<dim3(HH / 128, BB), 256, 81920>>>();

    // fused A_d2q + A_q2d, all 4 output slices
    gemm24f_mma<<<dim3(HH / 128, DD / 128, BB), 256, 208896>>>(Ud, out);
}

// round 9
// speedup vs baseline: 1.4745x; 1.2779x over previous
#include <cuda_runtime.h>
#include <cuda_bf16.h>
#include <cstdint>

#define BB 16
#define DD 1024
#define QQ 128
#define HH 1024

// ---------------- scratch (device globals) ----------------------------------
__device__ float g_S [BB * DD * QQ];
__device__ float g_sq[BB * QQ];
__device__ float g_cmax[BB * 8 * 128];
__device__ float g_csum[BB * 8 * 128];
// bf16 hi/lo operand arrays (all NATURAL orientation)
__device__ __nv_bfloat16 g_Uqwh[BB * QQ * HH], g_Uqwl[BB * QQ * HH];  // Uq*wdot [b,q,h]
__device__ __nv_bfloat16 g_Uqph[BB * QQ * HH], g_Uqpl[BB * QQ * HH];  // Uq plain [b,q,h]
__device__ __nv_bfloat16 g_P1h [BB * DD * QQ], g_P1l [BB * DD * QQ];  // S_d2q [b,d,q]
__device__ __nv_bfloat16 g_P2th[BB * QQ * DD], g_P2tl[BB * QQ * DD];  // S_q2d^T [b,q,d]
__device__ __nv_bfloat16 g_Th  [BB * QQ * HH], g_Tl  [BB * QQ * HH];  // T [b,q,h]

// ---------------- helpers ----------------------------------------------------
__device__ __forceinline__ uint32_t smem_u32(const void* p) {
    uint32_t a;
    asm("{ .reg .u64 t; cvta.to.shared.u64 t, %1; cvt.u32.u64 %0, t; }" : "=r"(a) : "l"(p));
    return a;
}
__device__ __forceinline__ uint32_t L32(const __nv_bfloat16* p) {
    return *(const uint32_t*)p;
}
__device__ __forceinline__ void mma_bf16(float* c, const uint32_t* a, const uint32_t* b) {
    asm volatile(
        "mma.sync.aligned.m16n8k16.row.col.f32.bf16.bf16.f32 "
        "{%0,%1,%2,%3}, {%4,%5,%6,%7}, {%8,%9}, {%0,%1,%2,%3};"
        : "+f"(c[0]), "+f"(c[1]), "+f"(c[2]), "+f"(c[3])
        : "r"(a[0]), "r"(a[1]), "r"(a[2]), "r"(a[3]), "r"(b[0]), "r"(b[1]));
}
__device__ __forceinline__ void ldmx4t(uint32_t& r0, uint32_t& r1,
                                       uint32_t& r2, uint32_t& r3, uint32_t a) {
    asm volatile("ldmatrix.sync.aligned.m8n8.x4.trans.shared.b16 {%0,%1,%2,%3}, [%4];"
        : "=r"(r0), "=r"(r1), "=r"(r2), "=r"(r3) : "r"(a));
}
__device__ __forceinline__ void bsplit(float x, __nv_bfloat16& h, __nv_bfloat16& l) {
    h = __float2bfloat16(x);
    l = __float2bfloat16(x - __bfloat162float(h));
}
#define CPA16(sa, g) \
    asm volatile("cp.async.cg.shared.global [%0], [%1], 16;" :: "r"(sa), "l"(g))
#define CPA_COMMIT() asm volatile("cp.async.commit_group;" ::: "memory")
#define CPA_WAIT0()  asm volatile("cp.async.wait_group 0;" ::: "memory")

// A fragments (K-contiguous layout, stride ST)
#define LOAD_AFRAGS(sAh, sAl, ST)                                             \
    uint32_t ah[4][4], al[4][4];                                              \
    _Pragma("unroll")                                                         \
    for (int i = 0; i < 4; i++) {                                             \
        int r = wm * 64 + i * 16 + gr;                                        \
        const __nv_bfloat16* p = (sAh) + r * (ST) + kb + 2 * qp;              \
        const __nv_bfloat16* q = (sAl) + r * (ST) + kb + 2 * qp;              \
        ah[i][0] = L32(p);            ah[i][1] = L32(p + 8 * (ST));           \
        ah[i][2] = L32(p + 8);        ah[i][3] = L32(p + 8 * (ST) + 8);       \
        al[i][0] = L32(q);            al[i][1] = L32(q + 8 * (ST));           \
        al[i][2] = L32(q + 8);        al[i][3] = L32(q + 8 * (ST) + 8);       \
    }

#define MMA3PASS(ACC, BH, BL)                                                 \
    _Pragma("unroll")                                                         \
    for (int i = 0; i < 4; i++)                                               \
        _Pragma("unroll")                                                     \
        for (int j = 0; j < 4; j++) mma_bf16((ACC)[i][j], ah[i], (BH)[j]);    \
    _Pragma("unroll")                                                         \
    for (int i = 0; i < 4; i++)                                               \
        _Pragma("unroll")                                                     \
        for (int j = 0; j < 4; j++) mma_bf16((ACC)[i][j], ah[i], (BL)[j]);    \
    _Pragma("unroll")                                                         \
    for (int i = 0; i < 4; i++)                                               \
        _Pragma("unroll")                                                     \
        for (int j = 0; j < 4; j++) mma_bf16((ACC)[i][j], al[i], (BH)[j]);

// K-contiguous B fragments (for gemm1)
#define LOAD_BFRAGS_K(sBh, sBl, ST, BH, BL)                                   \
    _Pragma("unroll")                                                         \
    for (int j = 0; j < 4; j++) {                                             \
        int c = wn * 32 + j * 8 + gr;                                         \
        const __nv_bfloat16* p = (sBh) + c * (ST) + kb + 2 * qp;              \
        const __nv_bfloat16* q = (sBl) + c * (ST) + kb + 2 * qp;              \
        BH[j][0] = L32(p); BH[j][1] = L32(p + 8);                             \
        BL[j][0] = L32(q); BL[j][1] = L32(q + 8);                             \
    }

// [k][n]-layout B fragments via ldmatrix.trans (stride STB elems, base u32)
#define LOAD_BFRAGS_T(bBh, bBl, STB, BH, BL)                                  \
    _Pragma("unroll")                                                         \
    for (int jj = 0; jj < 2; jj++) {                                          \
        int c0 = wn * 32 + jj * 16;                                           \
        uint32_t off = (uint32_t)(((kb + (lane & 15)) * (STB) + c0 +          \
                                   ((lane >> 4) * 8)) * 2);                   \
        ldmx4t(BH[2*jj][0], BH[2*jj][1], BH[2*jj+1][0], BH[2*jj+1][1], (bBh) + off); \
        ldmx4t(BL[2*jj][0], BL[2*jj][1], BL[2*jj+1][0], BL[2*jj+1][1], (bBl) + off); \
    }

#define GEMM_IDS                                                              \
    int t = threadIdx.x;                                                      \
    int wid = t >> 5, lane = t & 31;                                          \
    int wm = wid >> 2, wn = wid & 3;                                          \
    int gr = lane >> 2, qp = lane & 3;                                        \
    int srow = t >> 2, srow2 = (t >> 2) + 64, kc = (t & 3) * 8;

#define ACC_INIT(A)                                                           \
    _Pragma("unroll")                                                         \
    for (int i = 0; i < 4; i++)                                               \
        _Pragma("unroll")                                                     \
        for (int j = 0; j < 4; j++)                                           \
            _Pragma("unroll")                                                 \
            for (int e = 0; e < 4; e++) (A)[i][j][e] = 0.f;

// ---------------- conv_uq: Uq -> Uqw(hi/lo) + Uqp(hi/lo), plus s_q -----------
__global__ void conv_uq_kernel(const float* __restrict__ Uq,
                               const float* __restrict__ wcw) {
    __shared__ float red[8];
    int row = blockIdx.x;                 // b*QQ + q
    int t = threadIdx.x;
    const float* src = Uq + (size_t)row * HH;
    float4 v = *(const float4*)(src + t * 4);
    float4 wd = *(const float4*)(wcw + 2 * HH + t * 4);
    float4 wq = *(const float4*)(wcw + HH + t * 4);
    // plain split
    __nv_bfloat16 h0, l0, h1, l1, h2, l2, h3, l3;
    bsplit(v.x, h0, l0); bsplit(v.y, h1, l1);
    bsplit(v.z, h2, l2); bsplit(v.w, h3, l3);
    size_t o = (size_t)row * HH + t * 4;
    *(__nv_bfloat162*)(g_Uqph + o)     = __nv_bfloat162(h0, h1);
    *(__nv_bfloat162*)(g_Uqph + o + 2) = __nv_bfloat162(h2, h3);
    *(__nv_bfloat162*)(g_Uqpl + o)     = __nv_bfloat162(l0, l1);
    *(__nv_bfloat162*)(g_Uqpl + o + 2) = __nv_bfloat162(l2, l3);
    // wdot-scaled split
    float4 s = make_float4(v.x * wd.x, v.y * wd.y, v.z * wd.z, v.w * wd.w);
    bsplit(s.x, h0, l0); bsplit(s.y, h1, l1);
    bsplit(s.z, h2, l2); bsplit(s.w, h3, l3);
    *(__nv_bfloat162*)(g_Uqwh + o)     = __nv_bfloat162(h0, h1);
    *(__nv_bfloat162*)(g_Uqwh + o + 2) = __nv_bfloat162(h2, h3);
    *(__nv_bfloat162*)(g_Uqwl + o)     = __nv_bfloat162(l0, l1);
    *(__nv_bfloat162*)(g_Uqwl + o + 2) = __nv_bfloat162(l2, l3);
    // s_q partial dot
    float p = v.x * wq.x + v.y * wq.y + v.z * wq.z + v.w * wq.w;
    #pragma unroll
    for (int off = 16; off; off >>= 1) p += __shfl_xor_sync(0xffffffffu, p, off);
    if ((t & 31) == 0) red[t >> 5] = p;
    __syncthreads();
    if (t == 0) {
        float sum = 0.f;
        #pragma unroll
        for (int j = 0; j < 8; j++) sum += red[j];
        g_sq[row] = sum;
    }
}

// ---------------- GEMM1 fused: S, P1 (row softmax), col partials, s_d --------
__global__ __launch_bounds__(256) void gemm1_mma(
    const float* __restrict__ Ud, const float* __restrict__ wcw,
    const float* __restrict__ wcb,
    const int* __restrict__ qm, const int* __restrict__ dmk) {
    extern __shared__ __nv_bfloat16 dyn[];
    __shared__ float redM[128][4], redS[128][4];
    __shared__ float2 colp[2][128];
    __shared__ int s_qm[128];
    __shared__ float s_sdv[128];
    __shared__ float s_wd[HH];
    GEMM_IDS
    int b = blockIdx.y, m0 = blockIdx.x * 128;
    const float* A = Ud + (size_t)b * DD * HH + (size_t)m0 * HH;
    const __nv_bfloat16* Bh = g_Uqwh + (size_t)b * QQ * HH;
    const __nv_bfloat16* Bl = g_Uqwl + (size_t)b * QQ * HH;
    float acc[4][4][4];
    ACC_INIT(acc)
    float sdp[4] = {0.f, 0.f, 0.f, 0.f};
    if (t < 128) s_qm[t] = qm[b * QQ + t];
    #pragma unroll
    for (int i = t; i < HH; i += 256) s_wd[i] = wcw[i];
    uint32_t sbB0 = smem_u32(dyn) + 40960;

    float4 pref[4];
    #pragma unroll
    for (int v = 0; v < 4; v++) {
        int idx = v * 256 + t;
        pref[v] = *(const float4*)(A + (size_t)(idx >> 3) * HH + (idx & 7) * 4);
    }
    CPA16(sbB0 +         srow  * 80 + kc * 2, Bh + (size_t)srow  * HH + kc);
    CPA16(sbB0 +         srow2 * 80 + kc * 2, Bh + (size_t)srow2 * HH + kc);
    CPA16(sbB0 + 10240 + srow  * 80 + kc * 2, Bl + (size_t)srow  * HH + kc);
    CPA16(sbB0 + 10240 + srow2 * 80 + kc * 2, Bl + (size_t)srow2 * HH + kc);
    CPA_COMMIT();
    __syncthreads();   // s_wd ready

    for (int it = 0; it < HH / 32; it++) {
        CPA_WAIT0();
        __nv_bfloat16* As = dyn + (it & 1) * 10240;
        #pragma unroll
        for (int v = 0; v < 4; v++) {
            int idx = v * 256 + t;
            int row = idx >> 3, cs = (idx & 7) * 4;
            float4 x = pref[v];
            float4 w = *(const float4*)(s_wd + it * 32 + cs);
            sdp[v] += x.x * w.x + x.y * w.y + x.z * w.z + x.w * w.w;
            __nv_bfloat16 h0, l0, h1, l1, h2, l2, h3, l3;
            bsplit(x.x, h0, l0); bsplit(x.y, h1, l1);
            bsplit(x.z, h2, l2); bsplit(x.w, h3, l3);
            *(__nv_bfloat162*)(As + row * 40 + cs)            = __nv_bfloat162(h0, h1);
            *(__nv_bfloat162*)(As + row * 40 + cs + 2)        = __nv_bfloat162(h2, h3);
            *(__nv_bfloat162*)(As + 5120 + row * 40 + cs)     = __nv_bfloat162(l0, l1);
            *(__nv_bfloat162*)(As + 5120 + row * 40 + cs + 2) = __nv_bfloat162(l2, l3);
        }
        __syncthreads();
        if (it + 1 < HH / 32) {
            int k0 = (it + 1) * 32;
            uint32_t sbB = sbB0 + ((it + 1) & 1) * 20480;
            CPA16(sbB +         srow  * 80 + kc * 2, Bh + (size_t)srow  * HH + k0 + kc);
            CPA16(sbB +         srow2 * 80 + kc * 2, Bh + (size_t)srow2 * HH + k0 + kc);
            CPA16(sbB + 10240 + srow  * 80 + kc * 2, Bl + (size_t)srow  * HH + k0 + kc);
            CPA16(sbB + 10240 + srow2 * 80 + kc * 2, Bl + (size_t)srow2 * HH + k0 + kc);
            CPA_COMMIT();
            #pragma unroll
            for (int v = 0; v < 4; v++) {
                int idx = v * 256 + t;
                pref[v] = *(const float4*)(A + (size_t)(idx >> 3) * HH + k0 + (idx & 7) * 4);
            }
        }
        const __nv_bfloat16* cA = dyn + (it & 1) * 10240;
        const __nv_bfloat16* cB = dyn + 20480 + (it & 1) * 10240;
        #pragma unroll
        for (int kb = 0; kb < 32; kb += 16) {
            LOAD_AFRAGS(cA, cA + 5120, 40)
            uint32_t bh[4][2], bl[4][2];
            LOAD_BFRAGS_K(cB, cB + 5120, 40, bh, bl)
            MMA3PASS(acc, bh, bl)
        }
    }

    // s_d reduce (8 lanes share a row)
    #pragma unroll
    for (int v = 0; v < 4; v++) {
        float s = sdp[v];
        s += __shfl_xor_sync(0xffffffffu, s, 1);
        s += __shfl_xor_sync(0xffffffffu, s, 2);
        s += __shfl_xor_sync(0xffffffffu, s, 4);
        if ((lane & 7) == 0) s_sdv[v * 32 + (t >> 3)] = s;
    }

    float bias = wcb[0];
    int dmv[4][2];
    #pragma unroll
    for (int i = 0; i < 4; i++)
        #pragma unroll
        for (int rr = 0; rr < 2; rr++)
            dmv[i][rr] = dmk[b * DD + m0 + wm * 64 + i * 16 + rr * 8 + gr];
    __syncthreads();   // s_sdv + s_qm ready
    float sdv[4][2];
    #pragma unroll
    for (int i = 0; i < 4; i++)
        #pragma unroll
        for (int rr = 0; rr < 2; rr++)
            sdv[i][rr] = s_sdv[wm * 64 + i * 16 + rr * 8 + gr] + bias;

    #pragma unroll
    for (int i = 0; i < 4; i++)
        #pragma unroll
        for (int j = 0; j < 4; j++) {
            int n = wn * 32 + j * 8 + 2 * qp;
            float sq0 = g_sq[b * QQ + n], sq1 = g_sq[b * QQ + n + 1];
            int q0 = s_qm[n] > 0, q1 = s_qm[n + 1] > 0;
            #pragma unroll
            for (int rr = 0; rr < 2; rr++) {
                int m = m0 + wm * 64 + i * 16 + rr * 8 + gr;
                float s0 = acc[i][j][2 * rr]     + sdv[i][rr] + sq0;
                float s1 = acc[i][j][2 * rr + 1] + sdv[i][rr] + sq1;
                *(float2*)(g_S + ((size_t)b * DD + m) * QQ + n) = make_float2(s0, s1);
                int dm = dmv[i][rr] > 0;
                acc[i][j][2 * rr]     = (dm && q0) ? s0 : -1e30f;
                acc[i][j][2 * rr + 1] = (dm && q1) ? s1 : -1e30f;
            }
        }

    // row softmax max
    float M[4][2];
    #pragma unroll
    for (int i = 0; i < 4; i++)
        #pragma unroll
        for (int rr = 0; rr < 2; rr++) {
            float mx = -1e30f;
            #pragma unroll
            for (int j = 0; j < 4; j++)
                mx = fmaxf(mx, fmaxf(acc[i][j][2 * rr], acc[i][j][2 * rr + 1]));
            mx = fmaxf(mx, __shfl_xor_sync(0xffffffffu, mx, 1));
            mx = fmaxf(mx, __shfl_xor_sync(0xffffffffu, mx, 2));
            if (qp == 0) redM[wm * 64 + i * 16 + rr * 8 + gr][wn] = mx;
        }
    __syncthreads();
    #pragma unroll
    for (int i = 0; i < 4; i++)
        #pragma unroll
        for (int rr = 0; rr < 2; rr++) {
            int r = wm * 64 + i * 16 + rr * 8 + gr;
            M[i][rr] = fmaxf(fmaxf(redM[r][0], redM[r][1]),
                             fmaxf(redM[r][2], redM[r][3]));
        }
    // row softmax sum
    float inv[4][2];
    #pragma unroll
    for (int i = 0; i < 4; i++)
        #pragma unroll
        for (int rr = 0; rr < 2; rr++) {
            float s = 0.f;
            #pragma unroll
            for (int j = 0; j < 4; j++) {
                s += __expf(acc[i][j][2 * rr]     - M[i][rr]);
                s += __expf(acc[i][j][2 * rr + 1] - M[i][rr]);
            }
            s += __shfl_xor_sync(0xffffffffu, s, 1);
            s += __shfl_xor_sync(0xffffffffu, s, 2);
            if (qp == 0) redS[wm * 64 + i * 16 + rr * 8 + gr][wn] = s;
        }
    __syncthreads();
    #pragma unroll
    for (int i = 0; i < 4; i++)
        #pragma unroll
        for (int rr = 0; rr < 2; rr++) {
            int r = wm * 64 + i * 16 + rr * 8 + gr;
            inv[i][rr] = 1.f / (redS[r][0] + redS[r][1] + redS[r][2] + redS[r][3]);
        }
    // P1 write
    #pragma unroll
    for (int i = 0; i < 4; i++)
        #pragma unroll
        for (int j = 0; j < 4; j++) {
            int n = wn * 32 + j * 8 + 2 * qp;
            int q0 = s_qm[n] > 0, q1 = s_qm[n + 1] > 0;
            #pragma unroll
            for (int rr = 0; rr < 2; rr++) {
                int m = m0 + wm * 64 + i * 16 + rr * 8 + gr;
                int dm = dmv[i][rr] > 0;
                float p0 = (dm && q0) ? __expf(acc[i][j][2 * rr]     - M[i][rr]) * inv[i][rr] : 0.f;
                float p1 = (dm && q1) ? __expf(acc[i][j][2 * rr + 1] - M[i][rr]) * inv[i][rr] : 0.f;
                __nv_bfloat16 h0, l0, h1, l1;
                bsplit(p0, h0, l0); bsplit(p1, h1, l1);
                size_t o = ((size_t)b * DD + m) * QQ + n;
                *(__nv_bfloat162*)(g_P1h + o) = __nv_bfloat162(h0, h1);
                *(__nv_bfloat162*)(g_P1l + o) = __nv_bfloat162(l0, l1);
            }
        }
    // column partials
    #pragma unroll
    for (int j = 0; j < 4; j++)
        #pragma unroll
        for (int cc = 0; cc < 2; cc++) {
            float cm = -1e30f;
            #pragma unroll
            for (int i = 0; i < 4; i++)
                #pragma unroll
                for (int rr = 0; rr < 2; rr++)
                    cm = fmaxf(cm, acc[i][j][2 * rr + cc]);
            float cs = 0.f;
            #pragma unroll
            for (int i = 0; i < 4; i++)
                #pragma unroll
                for (int rr = 0; rr < 2; rr++)
                    cs += __expf(acc[i][j][2 * rr + cc] - cm);
            #pragma unroll
            for (int o = 4; o <= 16; o <<= 1) {
                float om = __shfl_xor_sync(0xffffffffu, cm, o);
                float os = __shfl_xor_sync(0xffffffffu, cs, o);
                float nm = fmaxf(cm, om);
                cs = cs * __expf(cm - nm) + os * __expf(om - nm);
                cm = nm;
            }
            if (gr == 0) colp[wm][wn * 32 + j * 8 + 2 * qp + cc] = make_float2(cm, cs);
        }
    __syncthreads();
    if (t < 128) {
        float2 a = colp[0][t], c = colp[1][t];
        float nm = fmaxf(a.x, c.x);
        float s = a.y * __expf(a.x - nm) + c.y * __expf(c.x - nm);
        int idx = (b * 8 + blockIdx.x) * 128 + t;
        g_cmax[idx] = nm; g_csum[idx] = s;
    }
}

// ---------------- single-pass q2d softmax -> P2t hi/lo -----------------------
__global__ void softmax_q2d_kernel(const int* __restrict__ qm,
                                   const int* __restrict__ dmk) {
    __shared__ float sM[32], sI[32];
    __shared__ float tile[32][33];
    int b = blockIdx.y;
    int tx = threadIdx.x, ty = threadIdx.y;
    int q = blockIdx.x * 32 + tx;
    int qmv = qm[b * QQ + q];
    int tid = ty * 32 + tx;
    if (tid < 32) {
        int qq = blockIdx.x * 32 + tid;
        float m = -1e30f, s = 0.f;
        #pragma unroll
        for (int k = 0; k < 8; k++) {
            float mk = g_cmax[(b * 8 + k) * 128 + qq];
            float sk = g_csum[(b * 8 + k) * 128 + qq];
            float nm = fmaxf(m, mk);
            s = s * __expf(m - nm) + sk * __expf(mk - nm);
            m = nm;
        }
        sM[tid] = m; sI[tid] = 1.f / s;
    }
    __syncthreads();
    float M = sM[tx], inv = sI[tx];
    const float* base = g_S + (size_t)b * DD * QQ + q;
    int qr = tid >> 3, seg = (tid & 7) * 4;
    size_t drow = (size_t)b * QQ * DD + (size_t)(blockIdx.x * 32 + qr) * DD;
    for (int d0 = 0; d0 < DD; d0 += 32) {
        #pragma unroll
        for (int dj = ty; dj < 32; dj += 8) {
            int d = d0 + dj;
            int mk = (qmv > 0) && (dmk[b * DD + d] > 0);
            float v = base[(size_t)d * QQ];
            tile[tx][dj] = mk ? __expf(v - M) * inv : 0.f;
        }
        __syncthreads();
        float p0 = tile[qr][seg], p1 = tile[qr][seg + 1];
        float p2 = tile[qr][seg + 2], p3 = tile[qr][seg + 3];
        __nv_bfloat16 h0, l0, h1, l1, h2, l2, h3, l3;
        bsplit(p0, h0, l0); bsplit(p1, h1, l1);
        bsplit(p2, h2, l2); bsplit(p3, h3, l3);
        size_t o = drow + d0 + seg;
        *(__nv_bfloat162*)(g_P2th + o)     = __nv_bfloat162(h0, h1);
        *(__nv_bfloat162*)(g_P2th + o + 2) = __nv_bfloat162(h2, h3);
        *(__nv_bfloat162*)(g_P2tl + o)     = __nv_bfloat162(l0, l1);
        *(__nv_bfloat162*)(g_P2tl + o + 2) = __nv_bfloat162(l2, l3);
        __syncthreads();
    }
}

// ---------------- GEMM3: T[q,h] = sum_d P2t[q,d] * Ud[d,h] -------------------
// A = P2t (cp.async, K-contig). B = fp32 Ud split in staging, [k=d][n=h],
// fragments via ldmatrix.trans. Output T hi/lo [q][h].
// stage layout (bytes): Ah 10240 | Al 10240 | Bh 8704 | Bl 8704 = 37888; x2.
__global__ __launch_bounds__(256) void gemm3_mma(const float* __restrict__ Ud) {
    extern __shared__ __nv_bfloat16 dyn[];
    GEMM_IDS
    int b = blockIdx.y, n0 = blockIdx.x * 128;
    const __nv_bfloat16* Ahg = g_P2th + (size_t)b * QQ * DD;
    const __nv_bfloat16* Alg = g_P2tl + (size_t)b * QQ * DD;
    const float* Bg = Ud + (size_t)b * DD * HH + n0;
    float acc[4][4][4];
    ACC_INIT(acc)
    uint32_t sb = smem_u32(dyn);

    // prologue: A(0) cp.async, B(0) regs
    CPA16(sb +         srow  * 80 + kc * 2, Ahg + (size_t)srow  * DD + kc);
    CPA16(sb +         srow2 * 80 + kc * 2, Ahg + (size_t)srow2 * DD + kc);
    CPA16(sb + 10240 + srow  * 80 + kc * 2, Alg + (size_t)srow  * DD + kc);
    CPA16(sb + 10240 + srow2 * 80 + kc * 2, Alg + (size_t)srow2 * DD + kc);
    CPA_COMMIT();
    float4 pref[4];
    #pragma unroll
    for (int v = 0; v < 4; v++) {
        int idx = v * 256 + t;
        pref[v] = *(const float4*)(Bg + (size_t)(idx >> 5) * HH + (idx & 31) * 4);
    }

    for (int it = 0; it < DD / 32; it++) {
        CPA_WAIT0();
        // stage B from regs (split), layout [d][h] stride 136
        __nv_bfloat16* Bs = dyn + (it & 1) * 18944 + 10240;
        #pragma unroll
        for (int v = 0; v < 4; v++) {
            int idx = v * 256 + t;
            int dr = idx >> 5, hc = (idx & 31) * 4;
            float4 x = pref[v];
            __nv_bfloat16 h0, l0, h1, l1, h2, l2, h3, l3;
            bsplit(x.x, h0, l0); bsplit(x.y, h1, l1);
            bsplit(x.z, h2, l2); bsplit(x.w, h3, l3);
            *(__nv_bfloat162*)(Bs + dr * 136 + hc)            = __nv_bfloat162(h0, h1);
            *(__nv_bfloat162*)(Bs + dr * 136 + hc + 2)        = __nv_bfloat162(h2, h3);
            *(__nv_bfloat162*)(Bs + 4352 + dr * 136 + hc)     = __nv_bfloat162(l0, l1);
            *(__nv_bfloat162*)(Bs + 4352 + dr * 136 + hc + 2) = __nv_bfloat162(l2, l3);
        }
        __syncthreads();
        if (it + 1 < DD / 32) {
            int k0 = (it + 1) * 32;
            uint32_t sbA = sb + ((it + 1) & 1) * 37888;
            CPA16(sbA +         srow  * 80 + kc * 2, Ahg + (size_t)srow  * DD + k0 + kc);
            CPA16(sbA +         srow2 * 80 + kc * 2, Ahg + (size_t)srow2 * DD + k0 + kc);
            CPA16(sbA + 10240 + srow  * 80 + kc * 2, Alg + (size_t)srow  * DD + k0 + kc);
            CPA16(sbA + 10240 + srow2 * 80 + kc * 2, Alg + (size_t)srow2 * DD + k0 + kc);
            CPA_COMMIT();
            #pragma unroll
            for (int v = 0; v < 4; v++) {
                int idx = v * 256 + t;
                pref[v] = *(const float4*)(Bg + (size_t)(k0 + (idx >> 5)) * HH + (idx & 31) * 4);
            }
        }
        const __nv_bfloat16* cA = dyn + (it & 1) * 18944;
        uint32_t bBh = sb + (it & 1) * 37888 + 20480;
        uint32_t bBl = bBh + 8704;
        #pragma unroll
        for (int kb = 0; kb < 32; kb += 16) {
            LOAD_AFRAGS(cA, cA + 5120, 40)
            uint32_t bh[4][2], bl[4][2];
            LOAD_BFRAGS_T(bBh, bBl, 136, bh, bl)
            MMA3PASS(acc, bh, bl)
        }
    }

    // epilogue: T[q][h] hi/lo
    #pragma unroll
    for (int i = 0; i < 4; i++) {
        int m = wm * 64 + i * 16 + gr;   // q
        #pragma unroll
        for (int j = 0; j < 4; j++) {
            int n = n0 + wn * 32 + j * 8 + 2 * qp;   // h
            #pragma unroll
            for (int rr = 0; rr < 2; rr++) {
                float a0 = acc[i][j][2 * rr], a1 = acc[i][j][2 * rr + 1];
                __nv_bfloat16 h0, l0, h1, l1;
                bsplit(a0, h0, l0); bsplit(a1, h1, l1);
                size_t o = ((size_t)b * QQ + m + rr * 8) * HH + n;
                *(__nv_bfloat162*)(g_Th + o) = __nv_bfloat162(h0, h1);
                *(__nv_bfloat162*)(g_Tl + o) = __nv_bfloat162(l0, l1);
            }
        }
    }
}

// ---------------- fused GEMM2+4: single-shot K=128 ---------------------------
#define ST24 136
#define TSZ  (128 * ST24)
__global__ __launch_bounds__(256) void gemm24f_mma(
    const float* __restrict__ Ud, float* __restrict__ out) {
    extern __shared__ __nv_bfloat16 dyn[];
    GEMM_IDS
    (void)srow; (void)srow2; (void)kc;
    int b = blockIdx.z, n0 = blockIdx.x * 128, m0 = blockIdx.y * 128;
    const __nv_bfloat16* srcs[6];
    int strides[6];
    srcs[0] = g_P1h  + (size_t)b * DD * QQ + (size_t)m0 * QQ; strides[0] = QQ;
    srcs[1] = g_P1l  + (size_t)b * DD * QQ + (size_t)m0 * QQ; strides[1] = QQ;
    srcs[2] = g_Uqph + (size_t)b * QQ * HH + n0;              strides[2] = HH;
    srcs[3] = g_Uqpl + (size_t)b * QQ * HH + n0;              strides[3] = HH;
    srcs[4] = g_Th   + (size_t)b * QQ * HH + n0;              strides[4] = HH;
    srcs[5] = g_Tl   + (size_t)b * QQ * HH + n0;              strides[5] = HH;

    uint32_t sb = smem_u32(dyn);
    #pragma unroll
    for (int v = 0; v < 8; v++) {
        int c = v * 256 + t;
        int row = c >> 4, kb8 = (c & 15) * 8;
        #pragma unroll
        for (int s = 0; s < 6; s++)
            CPA16(sb + s * (TSZ * 2) + row * (ST24 * 2) + kb8 * 2,
                  srcs[s] + (size_t)row * strides[s] + kb8);
    }
    CPA_COMMIT();
    CPA_WAIT0();
    __syncthreads();

    float acc2[4][4][4], acc4[4][4][4];
    ACC_INIT(acc2)
    ACC_INIT(acc4)
    const __nv_bfloat16* pA = dyn;
    uint32_t b2h = sb + 2 * (TSZ * 2), b2l = sb + 3 * (TSZ * 2);
    uint32_t b4h = sb + 4 * (TSZ * 2), b4l = sb + 5 * (TSZ * 2);
    #pragma unroll
    for (int s = 0; s < 8; s++) {
        int kb = s * 16;
        LOAD_AFRAGS(pA, pA + TSZ, ST24)
        {
            uint32_t bh[4][2], bl[4][2];
            LOAD_BFRAGS_T(b2h, b2l, ST24, bh, bl)
            MMA3PASS(acc2, bh, bl)
        }
        {
            uint32_t bh[4][2], bl[4][2];
            LOAD_BFRAGS_T(b4h, b4l, ST24, bh, bl)
            MMA3PASS(acc4, bh, bl)
        }
    }

    #pragma unroll
    for (int i = 0; i < 4; i++) {
        int m = m0 + wm * 64 + i * 16 + gr;
        #pragma unroll
        for (int j = 0; j < 4; j++) {
            int n = n0 + wn * 32 + j * 8 + 2 * qp;
            #pragma unroll
            for (int rr = 0; rr < 2; rr++) {
                int mm = m + rr * 8;
                float a2x = acc2[i][j][2 * rr], a2y = acc2[i][j][2 * rr + 1];
                float a4x = acc4[i][j][2 * rr], a4y = acc4[i][j][2 * rr + 1];
                float2 u = *(const float2*)(Ud + ((size_t)b * DD + mm) * HH + n);
                float* ob = out + ((size_t)b * DD + mm) * (size_t)(4 * HH) + n;
                *(float2*)(ob)          = u;
                *(float2*)(ob + HH)     = make_float2(a2x, a2y);
                *(float2*)(ob + 2 * HH) = make_float2(u.x * a2x, u.y * a2y);
                *(float2*)(ob + 3 * HH) = make_float2(u.x * a4x, u.y * a4y);
            }
        }
    }
}

// ---------------------------------------------------------------------------
extern "C" void kernel_launch(void* const* d_in, const int* in_sizes, int n_in,
                              void* d_out, int out_size) {
    const float* Ud  = (const float*)d_in[0];
    const float* Uq  = (const float*)d_in[1];
    const float* wcw = (const float*)d_in[2];
    const float* wcb = (const float*)d_in[3];
    const int*   qm  = (const int*)d_in[4];
    const int*   dmk = (const int*)d_in[5];
    float* out = (float*)d_out;

    cudaFuncSetAttribute(gemm1_mma,   cudaFuncAttributeMaxDynamicSharedMemorySize, 81920);
    cudaFuncSetAttribute(gemm3_mma,   cudaFuncAttributeMaxDynamicSharedMemorySize, 75776);
    cudaFuncSetAttribute(gemm24f_mma, cudaFuncAttributeMaxDynamicSharedMemorySize, 208896);

    // Uq splits (+ s_q)
    conv_uq_kernel<<<BB * QQ, 256>>>(Uq, wcw);

    // logits + row softmax + column partials + s_d
    gemm1_mma<<<dim3(DD / 128, BB), 256, 81920>>>(Ud, wcw, wcb, qm, dmk);

    // single-pass column softmax -> P2t
    softmax_q2d_kernel<<<dim3(QQ / 32, BB), dim3(32, 8)>>>(qm, dmk);

    // T = P2^T @ Ud  (in-kernel Ud split, trans-B fragments)
    gemm3_mma<<<dim3(HH / 128, BB), 256, 75776>>>(Ud);

    // fused A_d2q + A_q2d, all 4 output slices
    gemm24f_mma<<<dim3(HH / 128, DD / 128, BB), 256, 208896>>>(Ud, out);
}